// round 3
// baseline (speedup 1.0000x reference)
#include <cuda_runtime.h>
#include <math.h>

#define B_  64
#define T_  512
#define C_  512
#define NTC (T_ * C_)          // 262144 elems per batch
#define TOT (B_ * T_ * C_)     // 16777216

// Scratch (allocation-free rule: __device__ globals)
__device__ float g_bufA[TOT];   // X1 (LN1 out), later reused as H (gelu out)
__device__ float g_Y[TOT];      // tri-mix + tri_b + residual
__device__ float g_X2[TOT];     // LN2 out
__device__ float g_stats[4 * B_]; // mu1[64], rs1[64], mu2[64], rs2[64]

// ---------------------------------------------------------------------------
// Per-batch mean / rstd over T*C elements. One block per batch.
// ---------------------------------------------------------------------------
__global__ void stats_kernel(const float* __restrict__ x,
                             float* __restrict__ mu, float* __restrict__ rs) {
    int b = blockIdx.x;
    const float4* p = (const float4*)(x + (size_t)b * NTC);
    float s = 0.f, s2 = 0.f;
    for (int i = threadIdx.x; i < NTC / 4; i += blockDim.x) {
        float4 v = p[i];
        s  += v.x + v.y + v.z + v.w;
        s2 += v.x * v.x + v.y * v.y + v.z * v.z + v.w * v.w;
    }
    __shared__ float sh[512];
    __shared__ float sh2[512];
    sh[threadIdx.x] = s;
    sh2[threadIdx.x] = s2;
    __syncthreads();
    for (int o = blockDim.x / 2; o > 0; o >>= 1) {
        if (threadIdx.x < o) {
            sh[threadIdx.x]  += sh[threadIdx.x + o];
            sh2[threadIdx.x] += sh2[threadIdx.x + o];
        }
        __syncthreads();
    }
    if (threadIdx.x == 0) {
        float m   = sh[0] / (float)NTC;
        float var = sh2[0] / (float)NTC - m * m;
        mu[b] = m;
        rs[b] = rsqrtf(var + 1e-5f);
    }
}

// ---------------------------------------------------------------------------
// out[b,t,c] = (x[b,t,c] - mu[b]) * rs[b] * w[t,c] + bias[t,c]
// ---------------------------------------------------------------------------
__global__ void ln_apply(const float* __restrict__ x,
                         const float* __restrict__ w,
                         const float* __restrict__ bias,
                         const float* __restrict__ mu,
                         const float* __restrict__ rs,
                         float* __restrict__ out) {
    int b = blockIdx.y;
    int idx = blockIdx.x * blockDim.x + threadIdx.x;   // float4 index in [0, NTC/4)
    float m = mu[b], r = rs[b];
    float4 xv = ((const float4*)(x + (size_t)b * NTC))[idx];
    float4 wv = ((const float4*)w)[idx];
    float4 bv = ((const float4*)bias)[idx];
    float4 o;
    o.x = (xv.x - m) * r * wv.x + bv.x;
    o.y = (xv.y - m) * r * wv.y + bv.y;
    o.z = (xv.z - m) * r * wv.z + bv.z;
    o.w = (xv.w - m) * r * wv.w + bv.w;
    ((float4*)(out + (size_t)b * NTC))[idx] = o;
}

// ---------------------------------------------------------------------------
// Dense NT GEMM: Out[m,n] = epilogue( sum_k A[m,k] * W[n,k] )
// 128x128 tile, BK=16, 256 threads, 8x8 micro-tile in 2x2 blocks of 4x4.
// EPI==1: gelu(acc + bias[n]);  EPI==2: acc + bias[n] + Res[m,n]
// ---------------------------------------------------------------------------
template <int EPI>
__global__ __launch_bounds__(256, 2)
void gemm128(const float* __restrict__ A, const float* __restrict__ W,
             const float* __restrict__ bias, const float* __restrict__ Res,
             float* __restrict__ Out, int M, int K, int N) {
    __shared__ float As[16][132];
    __shared__ float Bs[16][132];
    int tid = threadIdx.x;
    int m0 = blockIdx.y * 128;
    int n0 = blockIdx.x * 128;

    float acc[8][8];
#pragma unroll
    for (int i = 0; i < 8; i++)
#pragma unroll
        for (int j = 0; j < 8; j++) acc[i][j] = 0.f;

    int lr = tid >> 2;            // 0..63
    int lc = (tid & 3) * 4;       // 0,4,8,12
    const float* Ap = A + (size_t)(m0 + lr) * K + lc;
    const float* Wp = W + (size_t)(n0 + lr) * K + lc;

    int rm = (tid >> 4) * 4;      // 0..60
    int rn = (tid & 15) * 4;      // 0..60

    for (int k0 = 0; k0 < K; k0 += 16) {
        float4 a0 = *(const float4*)(Ap + k0);
        float4 a1 = *(const float4*)(Ap + (size_t)64 * K + k0);
        float4 b0 = *(const float4*)(Wp + k0);
        float4 b1 = *(const float4*)(Wp + (size_t)64 * K + k0);
        As[lc + 0][lr] = a0.x; As[lc + 1][lr] = a0.y; As[lc + 2][lr] = a0.z; As[lc + 3][lr] = a0.w;
        As[lc + 0][lr + 64] = a1.x; As[lc + 1][lr + 64] = a1.y; As[lc + 2][lr + 64] = a1.z; As[lc + 3][lr + 64] = a1.w;
        Bs[lc + 0][lr] = b0.x; Bs[lc + 1][lr] = b0.y; Bs[lc + 2][lr] = b0.z; Bs[lc + 3][lr] = b0.w;
        Bs[lc + 0][lr + 64] = b1.x; Bs[lc + 1][lr + 64] = b1.y; Bs[lc + 2][lr + 64] = b1.z; Bs[lc + 3][lr + 64] = b1.w;
        __syncthreads();
#pragma unroll
        for (int kk = 0; kk < 16; kk++) {
            float4 t0 = *(const float4*)&As[kk][rm];
            float4 t1 = *(const float4*)&As[kk][rm + 64];
            float4 u0 = *(const float4*)&Bs[kk][rn];
            float4 u1 = *(const float4*)&Bs[kk][rn + 64];
            float av[8] = {t0.x, t0.y, t0.z, t0.w, t1.x, t1.y, t1.z, t1.w};
            float bv[8] = {u0.x, u0.y, u0.z, u0.w, u1.x, u1.y, u1.z, u1.w};
#pragma unroll
            for (int i = 0; i < 8; i++)
#pragma unroll
                for (int j = 0; j < 8; j++)
                    acc[i][j] = fmaf(av[i], bv[j], acc[i][j]);
        }
        __syncthreads();
    }

    float4 bias0 = *(const float4*)&bias[n0 + rn];
    float4 bias1 = *(const float4*)&bias[n0 + rn + 64];
    float bb[8] = {bias0.x, bias0.y, bias0.z, bias0.w, bias1.x, bias1.y, bias1.z, bias1.w};

#pragma unroll
    for (int i = 0; i < 8; i++) {
        int gm = m0 + ((i < 4) ? (rm + i) : (rm + 64 + i - 4));
        float* orow = Out + (size_t)gm * N + n0;
        const float* rrow = (EPI == 2) ? (Res + (size_t)gm * N + n0) : nullptr;
#pragma unroll
        for (int half = 0; half < 2; half++) {
            int cb = rn + half * 64;
            float4 o;
            float v[4];
#pragma unroll
            for (int j = 0; j < 4; j++) {
                float t = acc[i][half * 4 + j] + bb[half * 4 + j];
                if (EPI == 1) {
                    t = 0.5f * t * (1.0f + erff(t * 0.70710678118654752f));
                }
                v[j] = t;
            }
            if (EPI == 2) {
                float4 rv = *(const float4*)(rrow + cb);
                v[0] += rv.x; v[1] += rv.y; v[2] += rv.z; v[3] += rv.w;
            }
            o.x = v[0]; o.y = v[1]; o.z = v[2]; o.w = v[3];
            *(float4*)(orow + cb) = o;
        }
    }
}

// ---------------------------------------------------------------------------
// Triangular time-mix batched GEMM:
// Y[b,i,c] = sum_{j<=i} M[i,j] * X1[b,j,c] + tri_b[i] + inputs[b,i,c]
// K-loop truncated at the diagonal tile; mask applied on M loads.
// ---------------------------------------------------------------------------
__global__ __launch_bounds__(256, 2)
void trigemm(const float* __restrict__ Mtri, const float* __restrict__ X1,
             const float* __restrict__ tb, const float* __restrict__ resid,
             float* __restrict__ Y) {
    __shared__ float As[16][132];
    __shared__ float Bs[16][132];
    int tid = threadIdx.x;
    int b  = blockIdx.z;
    int i0 = blockIdx.y * 128;
    int c0 = blockIdx.x * 128;
    const float* Xb = X1 + (size_t)b * NTC;
    const float* Rb = resid + (size_t)b * NTC;
    float* Yb = Y + (size_t)b * NTC;

    float acc[8][8];
#pragma unroll
    for (int i = 0; i < 8; i++)
#pragma unroll
        for (int j = 0; j < 8; j++) acc[i][j] = 0.f;

    int lr = tid >> 2;
    int lc = (tid & 3) * 4;
    const float* Ap = Mtri + (size_t)(i0 + lr) * T_ + lc;

    int brow = tid >> 5;          // 0..7
    int bcol = (tid & 31) * 4;    // 0..124

    int rm = (tid >> 4) * 4;
    int rn = (tid & 15) * 4;

    int kend = i0 + 128;          // upper tri tiles skipped entirely
    for (int k0 = 0; k0 < kend; k0 += 16) {
        // A tile (M) with tril mask
        float4 a0 = *(const float4*)(Ap + k0);
        float4 a1 = *(const float4*)(Ap + (size_t)64 * T_ + k0);
        int iA = i0 + lr, iB = i0 + lr + 64, jb = k0 + lc;
        As[lc + 0][lr] = (jb + 0 <= iA) ? a0.x : 0.f;
        As[lc + 1][lr] = (jb + 1 <= iA) ? a0.y : 0.f;
        As[lc + 2][lr] = (jb + 2 <= iA) ? a0.z : 0.f;
        As[lc + 3][lr] = (jb + 3 <= iA) ? a0.w : 0.f;
        As[lc + 0][lr + 64] = (jb + 0 <= iB) ? a1.x : 0.f;
        As[lc + 1][lr + 64] = (jb + 1 <= iB) ? a1.y : 0.f;
        As[lc + 2][lr + 64] = (jb + 2 <= iB) ? a1.z : 0.f;
        As[lc + 3][lr + 64] = (jb + 3 <= iB) ? a1.w : 0.f;
        // B tile (X1 rows j, cols c) — already [k][n] layout, direct copy
        float4 x0 = *(const float4*)(Xb + (size_t)(k0 + brow) * C_ + c0 + bcol);
        float4 x1 = *(const float4*)(Xb + (size_t)(k0 + brow + 8) * C_ + c0 + bcol);
        *(float4*)&Bs[brow][bcol] = x0;
        *(float4*)&Bs[brow + 8][bcol] = x1;
        __syncthreads();
#pragma unroll
        for (int kk = 0; kk < 16; kk++) {
            float4 t0 = *(const float4*)&As[kk][rm];
            float4 t1 = *(const float4*)&As[kk][rm + 64];
            float4 u0 = *(const float4*)&Bs[kk][rn];
            float4 u1 = *(const float4*)&Bs[kk][rn + 64];
            float av[8] = {t0.x, t0.y, t0.z, t0.w, t1.x, t1.y, t1.z, t1.w};
            float bv[8] = {u0.x, u0.y, u0.z, u0.w, u1.x, u1.y, u1.z, u1.w};
#pragma unroll
            for (int i = 0; i < 8; i++)
#pragma unroll
                for (int j = 0; j < 8; j++)
                    acc[i][j] = fmaf(av[i], bv[j], acc[i][j]);
        }
        __syncthreads();
    }

#pragma unroll
    for (int i = 0; i < 8; i++) {
        int gi = i0 + ((i < 4) ? (rm + i) : (rm + 64 + i - 4));
        float tbi = tb[gi];
        float* orow = Yb + (size_t)gi * C_ + c0;
        const float* rrow = Rb + (size_t)gi * C_ + c0;
#pragma unroll
        for (int half = 0; half < 2; half++) {
            int cb = rn + half * 64;
            float4 rv = *(const float4*)(rrow + cb);
            float4 o;
            o.x = acc[i][half * 4 + 0] + tbi + rv.x;
            o.y = acc[i][half * 4 + 1] + tbi + rv.y;
            o.z = acc[i][half * 4 + 2] + tbi + rv.z;
            o.w = acc[i][half * 4 + 3] + tbi + rv.w;
            *(float4*)(orow + cb) = o;
        }
    }
}

// ---------------------------------------------------------------------------
extern "C" void kernel_launch(void* const* d_in, const int* in_sizes, int n_in,
                              void* d_out, int out_size) {
    const float* inputs = (const float*)d_in[0];
    const float* ln1w   = (const float*)d_in[1];
    const float* ln1b   = (const float*)d_in[2];
    const float* ln2w   = (const float*)d_in[3];
    const float* ln2b   = (const float*)d_in[4];
    const float* triM   = (const float*)d_in[5];
    const float* trib   = (const float*)d_in[6];
    const float* d1w    = (const float*)d_in[7];
    const float* d1b    = (const float*)d_in[8];
    const float* d2w    = (const float*)d_in[9];
    const float* d2b    = (const float*)d_in[10];
    float* out = (float*)d_out;

    float *bufA, *Ybuf, *X2buf, *stats;
    cudaGetSymbolAddress((void**)&bufA,  g_bufA);
    cudaGetSymbolAddress((void**)&Ybuf,  g_Y);
    cudaGetSymbolAddress((void**)&X2buf, g_X2);
    cudaGetSymbolAddress((void**)&stats, g_stats);
    float* mu1 = stats;
    float* rs1 = stats + B_;
    float* mu2 = stats + 2 * B_;
    float* rs2 = stats + 3 * B_;

    dim3 lnGrid(NTC / 4 / 256, B_);

    // 1) per-batch stats of inputs
    stats_kernel<<<B_, 512>>>(inputs, mu1, rs1);
    // 2) X1 = LN1(inputs)
    ln_apply<<<lnGrid, 256>>>(inputs, ln1w, ln1b, mu1, rs1, bufA);
    // 3) Y = tril(M) @ X1 + tri_b + inputs
    trigemm<<<dim3(C_ / 128, T_ / 128, B_), 256>>>(triM, bufA, trib, inputs, Ybuf);
    // 4) per-batch stats of Y
    stats_kernel<<<B_, 512>>>(Ybuf, mu2, rs2);
    // 5) X2 = LN2(Y)
    ln_apply<<<lnGrid, 256>>>(Ybuf, ln2w, ln2b, mu2, rs2, X2buf);
    // 6) H = gelu(X2 @ d1_w^T + d1_b)   (bufA reused as H)
    gemm128<1><<<dim3(C_ / 128, (B_ * T_) / 128), 256>>>(X2buf, d1w, d1b, nullptr, bufA,
                                                          B_ * T_, C_, C_);
    // 7) out = X2 + H @ d2_w^T + d2_b
    gemm128<2><<<dim3(C_ / 128, (B_ * T_) / 128), 256>>>(bufA, d2w, d2b, X2buf, out,
                                                          B_ * T_, C_, C_);
}

// round 12
// speedup vs baseline: 1.2421x; 1.2421x over previous
#include <cuda_runtime.h>
#include <cuda_bf16.h>
#include <math.h>
#include <stdint.h>

#define B_  64
#define T_  512
#define C_  512
#define NTC (T_ * C_)
#define TOT (B_ * T_ * C_)

// ---------------- scratch (__device__ globals; no allocation allowed) -------
__device__ float g_X1T[TOT];     // LN1 output, transposed [b][c][t]; reused as H
__device__ float g_Y[TOT];       // tri-mix output
__device__ float g_X2[TOT];      // LN2 output
__device__ float g_part[B_ * 16 * 2];
__device__ float g_stats[4 * B_];
__device__ __align__(16) __nv_bfloat16 g_mt_hi[T_ * T_];   // tril-masked Mtri
__device__ __align__(16) __nv_bfloat16 g_mt_lo[T_ * T_];
__device__ __align__(16) __nv_bfloat16 g_w1_hi[C_ * C_];
__device__ __align__(16) __nv_bfloat16 g_w1_lo[C_ * C_];
__device__ __align__(16) __nv_bfloat16 g_w2_hi[C_ * C_];
__device__ __align__(16) __nv_bfloat16 g_w2_lo[C_ * C_];

// ---------------- MMA helpers (sm_80-class PTX: valid on compute_103) -------
__device__ __forceinline__ uint32_t smem_u32(const void* p) {
    uint32_t a;
    asm("{ .reg .u64 t; cvta.to.shared.u64 t, %1; cvt.u32.u64 %0, t; }"
        : "=r"(a) : "l"(p));
    return a;
}
__device__ __forceinline__ void ldmx4(uint32_t* r, uint32_t a) {
    asm volatile("ldmatrix.sync.aligned.m8n8.x4.shared.b16 {%0,%1,%2,%3}, [%4];"
                 : "=r"(r[0]), "=r"(r[1]), "=r"(r[2]), "=r"(r[3]) : "r"(a));
}
__device__ __forceinline__ void mma16816(float* c, const uint32_t* a, const uint32_t* b) {
    asm volatile(
        "mma.sync.aligned.m16n8k16.row.col.f32.bf16.bf16.f32 "
        "{%0,%1,%2,%3}, {%4,%5,%6,%7}, {%8,%9}, {%0,%1,%2,%3};"
        : "+f"(c[0]), "+f"(c[1]), "+f"(c[2]), "+f"(c[3])
        : "r"(a[0]), "r"(a[1]), "r"(a[2]), "r"(a[3]), "r"(b[0]), "r"(b[1]));
}

// smem tile: 128 rows x 32 bf16 (64B) padded to 80B/row -> conflict-free ldmatrix
#define STRIDE   80
#define TILE_B   (128 * STRIDE)          // 10240
#define SM_A_HI  0
#define SM_A_LO  (1 * TILE_B)
#define SM_B_HI  (2 * TILE_B)
#define SM_B_LO  (3 * TILE_B)
#define STAGE_B  (4 * TILE_B)            // 40960
#define SMEM_GEMM_BYTES (2 * STAGE_B)    // 81920

// ---------------------------------------------------------------------------
// mma.sync GEMM: D[m,n] = sum_k A[m,k] * B[n,k], 128x128 tile, BK=32, K=512.
// fp32 emulated as 3-term bf16 split: Ahi*Bhi + Ahi*Blo + Alo*Bhi.
// A_BF16=true : A pre-split bf16 (tri: Mtri), B fp32 split in-kernel (X1T)
// A_BF16=false: A fp32 split in-kernel (acts), B pre-split bf16 (weights)
// MODE 0: out = acc + bias[m] + Res[m,n]   (tri; K truncated at diagonal tile)
// MODE 1: out = gelu(acc + bias[n])
// MODE 2: out = acc + bias[n] + Res[m,n]
// ---------------------------------------------------------------------------
template <bool A_BF16, int MODE>
__global__ __launch_bounds__(256, 1)
void gemm_mma(const float* Af, const __nv_bfloat16* AhiG, const __nv_bfloat16* AloG,
              const float* Bf, const __nv_bfloat16* BhiG, const __nv_bfloat16* BloG,
              const float* bias, const float* Res, float* Out,
              size_t aZ, size_t bZ, size_t oZ) {
    extern __shared__ char smem[];
    const int Kd = 512;
    int tid = threadIdx.x, wid = tid >> 5, lane = tid & 31;
    int n0 = blockIdx.x * 128, m0 = blockIdx.y * 128;
    size_t bz = blockIdx.z;

    if (A_BF16) { AhiG += bz * aZ; AloG += bz * aZ; Bf += bz * bZ; }
    else        { Af += bz * aZ; BhiG += bz * bZ; BloG += bz * bZ; }
    if (MODE != 1) Res += bz * oZ;
    Out += bz * oZ;

    uint32_t sb = smem_u32(smem);

    float acc[4][4][4];
#pragma unroll
    for (int i = 0; i < 4; i++)
#pragma unroll
        for (int j = 0; j < 4; j++)
#pragma unroll
            for (int e = 0; e < 4; e++) acc[i][j][e] = 0.f;

    int kend = (MODE == 0) ? (m0 + 128) : Kd;
    int nch = kend / 32;

    // ---- producers ----------------------------------------------------
    // FIXED: 512 segs x 8 bf16 (one uint4) = full 128x32 tile coverage.
    auto load_bf16 = [&](const __nv_bfloat16* Hg, const __nv_bfloat16* Lg,
                         int row0, int dhi, int dlo, int k0) {
#pragma unroll
        for (int it = 0; it < 2; ++it) {
            int seg = tid + it * 256;                      // 0..511
            int r = seg >> 2, c8 = (seg & 3) * 8;          // 128 rows x 4 octets
            size_t go = (size_t)(row0 + r) * Kd + k0 + c8;
            uint4 hv = *(const uint4*)(Hg + go);           // 8 bf16 = 16B
            uint4 lv = *(const uint4*)(Lg + go);
            int off = r * STRIDE + c8 * 2;
            *(uint4*)(smem + dhi + off) = hv;
            *(uint4*)(smem + dlo + off) = lv;
        }
    };
    auto load_f32 = [&](const float* F, int row0, int dhi, int dlo, int k0) {
#pragma unroll
        for (int it = 0; it < 2; ++it) {
            int seg = tid + it * 256;                      // 0..511
            int r = seg >> 2, c8 = (seg & 3) * 8;          // 128 rows x 4 octets
            const float* p = F + (size_t)(row0 + r) * Kd + k0 + c8;
            float4 v0 = *(const float4*)p;
            float4 v1 = *(const float4*)(p + 4);
            float xs[8] = {v0.x, v0.y, v0.z, v0.w, v1.x, v1.y, v1.z, v1.w};
            uint32_t hw[4], lw[4];
#pragma unroll
            for (int e = 0; e < 4; ++e) {
                __nv_bfloat16 h0 = __float2bfloat16(xs[2 * e]);
                __nv_bfloat16 h1 = __float2bfloat16(xs[2 * e + 1]);
                __nv_bfloat16 g0 = __float2bfloat16(xs[2 * e] - __bfloat162float(h0));
                __nv_bfloat16 g1 = __float2bfloat16(xs[2 * e + 1] - __bfloat162float(h1));
                hw[e] = (uint32_t)__bfloat16_as_ushort(h0) |
                        ((uint32_t)__bfloat16_as_ushort(h1) << 16);
                lw[e] = (uint32_t)__bfloat16_as_ushort(g0) |
                        ((uint32_t)__bfloat16_as_ushort(g1) << 16);
            }
            int off = r * STRIDE + c8 * 2;
            *(uint4*)(smem + dhi + off) = make_uint4(hw[0], hw[1], hw[2], hw[3]);
            *(uint4*)(smem + dlo + off) = make_uint4(lw[0], lw[1], lw[2], lw[3]);
        }
    };
    auto load_chunk = [&](int c, int s) {
        int base = s * STAGE_B, k0 = c * 32;
        if (A_BF16) {
            load_bf16(AhiG, AloG, m0, base + SM_A_HI, base + SM_A_LO, k0);
            load_f32 (Bf,         n0, base + SM_B_HI, base + SM_B_LO, k0);
        } else {
            load_f32 (Af,         m0, base + SM_A_HI, base + SM_A_LO, k0);
            load_bf16(BhiG, BloG, n0, base + SM_B_HI, base + SM_B_LO, k0);
        }
    };

    // ---- per-lane ldmatrix bases ---------------------------------------
    // A frag (m16k16 row-major): mats: (m,k0),(m+8,k0),(m,k0+8),(m+8,k0+8)
    int aRow = (wid & 1) * 64 + ((lane >> 3) & 1) * 8 + (lane & 7);
    int aCol = (lane >> 4) * 16;                               // bytes
    // B frags (x4 covers two n8 blocks): mats: (n,k0),(n,k0+8),(n+8,k0),(n+8,k0+8)
    int bRow = (wid >> 1) * 32 + (lane >> 4) * 8 + (lane & 7);
    int bCol = ((lane >> 3) & 1) * 16;                         // bytes

    load_chunk(0, 0);
    __syncthreads();

    for (int c = 0; c < nch; ++c) {
        int s = c & 1;
        if (c + 1 < nch) load_chunk(c + 1, s ^ 1);

        uint32_t aHiB = sb + s * STAGE_B + SM_A_HI + aRow * STRIDE + aCol;
        uint32_t aLoB = aHiB + (SM_A_LO - SM_A_HI);
        uint32_t bHiB = sb + s * STAGE_B + SM_B_HI + bRow * STRIDE + bCol;
        uint32_t bLoB = bHiB + (SM_B_LO - SM_B_HI);

#pragma unroll
        for (int ks = 0; ks < 2; ++ks) {
            int kso = ks * 32;                                 // 16 bf16 = 32B
            uint32_t ah[4][4], al[4][4], bh[4][2], bl[4][2];
#pragma unroll
            for (int mi = 0; mi < 4; ++mi) {
                ldmx4(ah[mi], aHiB + mi * (16 * STRIDE) + kso);
                ldmx4(al[mi], aLoB + mi * (16 * STRIDE) + kso);
            }
#pragma unroll
            for (int jj = 0; jj < 2; ++jj) {
                uint32_t t4[4];
                ldmx4(t4, bHiB + jj * (16 * STRIDE) + kso);
                bh[2 * jj][0] = t4[0]; bh[2 * jj][1] = t4[1];
                bh[2 * jj + 1][0] = t4[2]; bh[2 * jj + 1][1] = t4[3];
                ldmx4(t4, bLoB + jj * (16 * STRIDE) + kso);
                bl[2 * jj][0] = t4[0]; bl[2 * jj][1] = t4[1];
                bl[2 * jj + 1][0] = t4[2]; bl[2 * jj + 1][1] = t4[3];
            }
#pragma unroll
            for (int mi = 0; mi < 4; ++mi)
#pragma unroll
                for (int ni = 0; ni < 4; ++ni) {
                    mma16816(acc[mi][ni], ah[mi], bh[ni]);
                    mma16816(acc[mi][ni], ah[mi], bl[ni]);
                    mma16816(acc[mi][ni], al[mi], bh[ni]);
                }
        }
        __syncthreads();
    }

    // ---- epilogue -------------------------------------------------------
    int mwb = m0 + (wid & 1) * 64;
    int nwb = n0 + (wid >> 1) * 32;
    int mr = lane >> 2, nc = (lane & 3) * 2;
#pragma unroll
    for (int mi = 0; mi < 4; ++mi) {
#pragma unroll
        for (int ni = 0; ni < 4; ++ni) {
            int n = nwb + ni * 8 + nc;
#pragma unroll
            for (int half = 0; half < 2; ++half) {
                int m = mwb + mi * 16 + mr + half * 8;
                float v0 = acc[mi][ni][half * 2 + 0];
                float v1 = acc[mi][ni][half * 2 + 1];
                if (MODE == 0) {
                    float tb = bias[m];
                    float2 rv = *(const float2*)(Res + (size_t)m * 512 + n);
                    v0 += tb + rv.x; v1 += tb + rv.y;
                } else if (MODE == 1) {
                    float2 bb = *(const float2*)(bias + n);
                    float t0 = v0 + bb.x, t1 = v1 + bb.y;
                    v0 = 0.5f * t0 * (1.0f + erff(t0 * 0.70710678118654752f));
                    v1 = 0.5f * t1 * (1.0f + erff(t1 * 0.70710678118654752f));
                } else {
                    float2 bb = *(const float2*)(bias + n);
                    float2 rv = *(const float2*)(Res + (size_t)m * 512 + n);
                    v0 += bb.x + rv.x; v1 += bb.y + rv.y;
                }
                *(float2*)(Out + (size_t)m * 512 + n) = make_float2(v0, v1);
            }
        }
    }
}

// ---------------------------------------------------------------------------
// Weight pre-split: fp32 -> bf16 (hi, lo); z=0 applies tril mask to Mtri.
// ---------------------------------------------------------------------------
__global__ void split_w(const float* __restrict__ Mt, const float* __restrict__ w1,
                        const float* __restrict__ w2) {
    int idx = blockIdx.x * 256 + threadIdx.x;   // 0..262143 (grid.x = 1024)
    int z = blockIdx.y;
    float v;
    __nv_bfloat16 *H, *L;
    if (z == 0) {
        int i = idx >> 9, j = idx & 511;
        v = (j <= i) ? Mt[idx] : 0.f;
        H = g_mt_hi; L = g_mt_lo;
    } else if (z == 1) {
        v = w1[idx]; H = g_w1_hi; L = g_w1_lo;
    } else {
        v = w2[idx]; H = g_w2_hi; L = g_w2_lo;
    }
    __nv_bfloat16 h = __float2bfloat16(v);
    H[idx] = h;
    L[idx] = __float2bfloat16(v - __bfloat162float(h));
}

// ---------------------------------------------------------------------------
// Per-batch stats, split 16 ways for occupancy (deterministic two-pass).
// ---------------------------------------------------------------------------
__global__ void stats_part(const float* __restrict__ x, float* __restrict__ part) {
    int b = blockIdx.y, slice = blockIdx.x;
    const float4* p = (const float4*)(x + (size_t)b * NTC) + (size_t)slice * 4096;
    float s = 0.f, s2 = 0.f;
    for (int i = threadIdx.x; i < 4096; i += 256) {
        float4 v = p[i];
        s  += v.x + v.y + v.z + v.w;
        s2 += v.x * v.x + v.y * v.y + v.z * v.z + v.w * v.w;
    }
    __shared__ float sh[256], sh2[256];
    sh[threadIdx.x] = s; sh2[threadIdx.x] = s2;
    __syncthreads();
    for (int o = 128; o > 0; o >>= 1) {
        if (threadIdx.x < o) {
            sh[threadIdx.x] += sh[threadIdx.x + o];
            sh2[threadIdx.x] += sh2[threadIdx.x + o];
        }
        __syncthreads();
    }
    if (threadIdx.x == 0) {
        part[(b * 16 + slice) * 2 + 0] = sh[0];
        part[(b * 16 + slice) * 2 + 1] = sh2[0];
    }
}
__global__ void stats_fin(const float* __restrict__ part, float* __restrict__ mu,
                          float* __restrict__ rs) {
    int b = threadIdx.x;
    float s = 0.f, s2 = 0.f;
    for (int i = 0; i < 16; ++i) {
        s  += part[(b * 16 + i) * 2 + 0];
        s2 += part[(b * 16 + i) * 2 + 1];
    }
    float m = s / (float)NTC;
    float var = s2 / (float)NTC - m * m;
    mu[b] = m;
    rs[b] = rsqrtf(var + 1e-5f);
}

// ---------------------------------------------------------------------------
// LN1 + transpose: X1T[b][c][t] = (x[b][t][c]-mu)*rs*w[t][c]+bias[t][c]
// ---------------------------------------------------------------------------
__global__ void ln1t(const float* __restrict__ x, const float* __restrict__ w,
                     const float* __restrict__ bias, const float* __restrict__ mu,
                     const float* __restrict__ rs, float* __restrict__ xt) {
    __shared__ float tile[32][33];
    int b = blockIdx.z;
    int t0 = blockIdx.x * 32, c0 = blockIdx.y * 32;
    float m = mu[b], r = rs[b];
    int tx = threadIdx.x, ty = threadIdx.y;
#pragma unroll
    for (int k = 0; k < 4; ++k) {
        int t = t0 + ty + k * 8, c = c0 + tx;
        size_t idx = (size_t)t * C_ + c;
        tile[ty + k * 8][tx] = (x[(size_t)b * NTC + idx] - m) * r * w[idx] + bias[idx];
    }
    __syncthreads();
#pragma unroll
    for (int k = 0; k < 4; ++k) {
        int c = c0 + ty + k * 8, t = t0 + tx;
        xt[(size_t)b * NTC + (size_t)c * T_ + t] = tile[tx][ty + k * 8];
    }
}

// ---------------------------------------------------------------------------
// Plain LN apply (no transpose), float4 vectorized.
// ---------------------------------------------------------------------------
__global__ void ln_apply(const float* __restrict__ x, const float* __restrict__ w,
                         const float* __restrict__ bias, const float* __restrict__ mu,
                         const float* __restrict__ rs, float* __restrict__ out) {
    int b = blockIdx.y;
    int idx = blockIdx.x * blockDim.x + threadIdx.x;
    float m = mu[b], r = rs[b];
    float4 xv = ((const float4*)(x + (size_t)b * NTC))[idx];
    float4 wv = ((const float4*)w)[idx];
    float4 bv = ((const float4*)bias)[idx];
    float4 o;
    o.x = (xv.x - m) * r * wv.x + bv.x;
    o.y = (xv.y - m) * r * wv.y + bv.y;
    o.z = (xv.z - m) * r * wv.z + bv.z;
    o.w = (xv.w - m) * r * wv.w + bv.w;
    ((float4*)(out + (size_t)b * NTC))[idx] = o;
}

// ---------------------------------------------------------------------------
extern "C" void kernel_launch(void* const* d_in, const int* in_sizes, int n_in,
                              void* d_out, int out_size) {
    const float* inputs = (const float*)d_in[0];
    const float* ln1w   = (const float*)d_in[1];
    const float* ln1b   = (const float*)d_in[2];
    const float* ln2w   = (const float*)d_in[3];
    const float* ln2b   = (const float*)d_in[4];
    const float* triM   = (const float*)d_in[5];
    const float* trib   = (const float*)d_in[6];
    const float* d1w    = (const float*)d_in[7];
    const float* d1b    = (const float*)d_in[8];
    const float* d2w    = (const float*)d_in[9];
    const float* d2b    = (const float*)d_in[10];
    float* out = (float*)d_out;

    float *X1T, *Ybuf, *X2buf, *part, *stats;
    __nv_bfloat16 *mth, *mtl, *w1h, *w1l, *w2h, *w2l;
    cudaGetSymbolAddress((void**)&X1T,   g_X1T);
    cudaGetSymbolAddress((void**)&Ybuf,  g_Y);
    cudaGetSymbolAddress((void**)&X2buf, g_X2);
    cudaGetSymbolAddress((void**)&part,  g_part);
    cudaGetSymbolAddress((void**)&stats, g_stats);
    cudaGetSymbolAddress((void**)&mth, g_mt_hi);
    cudaGetSymbolAddress((void**)&mtl, g_mt_lo);
    cudaGetSymbolAddress((void**)&w1h, g_w1_hi);
    cudaGetSymbolAddress((void**)&w1l, g_w1_lo);
    cudaGetSymbolAddress((void**)&w2h, g_w2_hi);
    cudaGetSymbolAddress((void**)&w2l, g_w2_lo);
    float* mu1 = stats;
    float* rs1 = stats + B_;
    float* mu2 = stats + 2 * B_;
    float* rs2 = stats + 3 * B_;

    cudaFuncSetAttribute(gemm_mma<true, 0>,
                         cudaFuncAttributeMaxDynamicSharedMemorySize, SMEM_GEMM_BYTES);
    cudaFuncSetAttribute(gemm_mma<false, 1>,
                         cudaFuncAttributeMaxDynamicSharedMemorySize, SMEM_GEMM_BYTES);
    cudaFuncSetAttribute(gemm_mma<false, 2>,
                         cudaFuncAttributeMaxDynamicSharedMemorySize, SMEM_GEMM_BYTES);

    // 0) pre-split weights (tril-masked Mtri, d1_w, d2_w) to bf16 hi/lo
    split_w<<<dim3(1024, 3), 256>>>(triM, d1w, d2w);

    // 1) stats of inputs
    stats_part<<<dim3(16, B_), 256>>>(inputs, part);
    stats_fin<<<1, B_>>>(part, mu1, rs1);

    // 2) X1T = transpose(LN1(inputs))
    ln1t<<<dim3(T_ / 32, C_ / 32, B_), dim3(32, 8)>>>(inputs, ln1w, ln1b, mu1, rs1, X1T);

    // 3) Y = tril(M) @ X1 + tri_b + inputs   (A = masked Mtri bf16, B = X1T fp32)
    gemm_mma<true, 0><<<dim3(4, 4, B_), 256, SMEM_GEMM_BYTES>>>(
        nullptr, mth, mtl, X1T, nullptr, nullptr,
        trib, inputs, Ybuf, 0, (size_t)NTC, (size_t)NTC);

    // 4) stats of Y
    stats_part<<<dim3(16, B_), 256>>>(Ybuf, part);
    stats_fin<<<1, B_>>>(part, mu2, rs2);

    // 5) X2 = LN2(Y)
    ln_apply<<<dim3(NTC / 4 / 256, B_), 256>>>(Ybuf, ln2w, ln2b, mu2, rs2, X2buf);

    // 6) H = gelu(X2 @ d1_w^T + d1_b)   (X1T buffer reused as H)
    gemm_mma<false, 1><<<dim3(4, 256, 1), 256, SMEM_GEMM_BYTES>>>(
        X2buf, nullptr, nullptr, nullptr, w1h, w1l,
        d1b, nullptr, X1T, 0, 0, 0);

    // 7) out = X2 + H @ d2_w^T + d2_b
    gemm_mma<false, 2><<<dim3(4, 256, 1), 256, SMEM_GEMM_BYTES>>>(
        X1T, nullptr, nullptr, nullptr, w2h, w2l,
        d2b, X2buf, out, 0, 0, 0);
}

// round 13
// speedup vs baseline: 1.5616x; 1.2572x over previous
#include <cuda_runtime.h>
#include <cuda_bf16.h>
#include <math.h>
#include <stdint.h>

#define B_  64
#define T_  512
#define C_  512
#define NTC (T_ * C_)
#define TOT (B_ * T_ * C_)

// ---------------- scratch (__device__ globals; no allocation allowed) -------
__device__ float g_Y[TOT];       // tri-mix output (fp32, LN2 input)
__device__ float g_X2[TOT];      // LN2 output fp32 (residual for final GEMM)
__device__ float g_part[B_ * 16 * 2];
__device__ float g_stats[4 * B_];
// pre-split bf16 operands (hi/lo)
__device__ __align__(16) __nv_bfloat16 g_x1t_hi[TOT], g_x1t_lo[TOT];  // LN1^T
__device__ __align__(16) __nv_bfloat16 g_x2_hi[TOT],  g_x2_lo[TOT];   // LN2
__device__ __align__(16) __nv_bfloat16 g_h_hi[TOT],   g_h_lo[TOT];    // gelu out
__device__ __align__(16) __nv_bfloat16 g_mt_hi[T_ * T_], g_mt_lo[T_ * T_];
__device__ __align__(16) __nv_bfloat16 g_w1_hi[C_ * C_], g_w1_lo[C_ * C_];
__device__ __align__(16) __nv_bfloat16 g_w2_hi[C_ * C_], g_w2_lo[C_ * C_];

// ---------------- PTX helpers (sm_80-class: valid on compute_103) ----------
__device__ __forceinline__ uint32_t smem_u32(const void* p) {
    uint32_t a;
    asm("{ .reg .u64 t; cvta.to.shared.u64 t, %1; cvt.u32.u64 %0, t; }"
        : "=r"(a) : "l"(p));
    return a;
}
__device__ __forceinline__ void ldmx4(uint32_t* r, uint32_t a) {
    asm volatile("ldmatrix.sync.aligned.m8n8.x4.shared.b16 {%0,%1,%2,%3}, [%4];"
                 : "=r"(r[0]), "=r"(r[1]), "=r"(r[2]), "=r"(r[3]) : "r"(a));
}
__device__ __forceinline__ void mma16816(float* c, const uint32_t* a, const uint32_t* b) {
    asm volatile(
        "mma.sync.aligned.m16n8k16.row.col.f32.bf16.bf16.f32 "
        "{%0,%1,%2,%3}, {%4,%5,%6,%7}, {%8,%9}, {%0,%1,%2,%3};"
        : "+f"(c[0]), "+f"(c[1]), "+f"(c[2]), "+f"(c[3])
        : "r"(a[0]), "r"(a[1]), "r"(a[2]), "r"(a[3]), "r"(b[0]), "r"(b[1]));
}
__device__ __forceinline__ void cp16(uint32_t sdst, const void* gsrc) {
    asm volatile("cp.async.cg.shared.global [%0], [%1], 16;"
                 :: "r"(sdst), "l"(gsrc));
}
#define CP_COMMIT() asm volatile("cp.async.commit_group;" ::: "memory")
#define CP_WAIT(n)  asm volatile("cp.async.wait_group %0;" :: "n"(n) : "memory")

// smem tile: 128 rows x 32 bf16 (64B) padded to 80B/row (16B-aligned, no conflicts)
#define STRIDE   80
#define TILE_B   (128 * STRIDE)          // 10240
#define SM_A_HI  0
#define SM_A_LO  (1 * TILE_B)
#define SM_B_HI  (2 * TILE_B)
#define SM_B_LO  (3 * TILE_B)
#define STAGE_B  (4 * TILE_B)            // 40960
#define SMEM_GEMM_BYTES (2 * STAGE_B)    // 81920

// ---------------------------------------------------------------------------
// mma.sync GEMM: D[m,n] = sum_k A[m,k]*B[n,k], 128x128 tile, BK=32, K=512.
// All operands pre-split bf16 hi/lo; 3-term: Ah*Bh + Ah*Bl + Al*Bh.
// MODE 0: OutF = acc + bias[m] + Res[m,n]     (tri; K truncated at diag tile)
// MODE 1: gelu(acc + bias[n]) -> split -> OutHi/OutLo (bf16)
// MODE 2: OutF = acc + bias[n] + Res[m,n]
// ---------------------------------------------------------------------------
template <int MODE>
__global__ __launch_bounds__(256, 1)
void gemm_mma(const __nv_bfloat16* AhiG, const __nv_bfloat16* AloG,
              const __nv_bfloat16* BhiG, const __nv_bfloat16* BloG,
              const float* bias, const float* Res, float* OutF,
              __nv_bfloat16* OutHi, __nv_bfloat16* OutLo,
              size_t aZ, size_t bZ, size_t oZ) {
    extern __shared__ char smem[];
    const int Kd = 512;
    int tid = threadIdx.x, wid = tid >> 5, lane = tid & 31;
    int n0 = blockIdx.x * 128, m0 = blockIdx.y * 128;
    size_t bz = blockIdx.z;

    AhiG += bz * aZ; AloG += bz * aZ;
    BhiG += bz * bZ; BloG += bz * bZ;
    if (MODE != 1) { Res += bz * oZ; OutF += bz * oZ; }

    uint32_t sb = smem_u32(smem);

    float acc[4][4][4];
#pragma unroll
    for (int i = 0; i < 4; i++)
#pragma unroll
        for (int j = 0; j < 4; j++)
#pragma unroll
            for (int e = 0; e < 4; e++) acc[i][j][e] = 0.f;

    int kend = (MODE == 0) ? (m0 + 128) : Kd;
    int nch = kend / 32;

    // ---- producers: pure cp.async copies (8 x 16B per thread per chunk) ---
    auto load_pair = [&](const __nv_bfloat16* Hg, const __nv_bfloat16* Lg,
                         int row0, uint32_t dhi, uint32_t dlo, int k0) {
#pragma unroll
        for (int it = 0; it < 2; ++it) {
            int seg = tid + it * 256;                  // 0..511
            int r = seg >> 2, c8 = (seg & 3) * 8;      // 128 rows x 4 octets
            size_t go = (size_t)(row0 + r) * Kd + k0 + c8;
            uint32_t off = (uint32_t)(r * STRIDE + c8 * 2);
            cp16(dhi + off, Hg + go);
            cp16(dlo + off, Lg + go);
        }
    };
    auto load_chunk = [&](int c, int s) {
        uint32_t base = sb + s * STAGE_B;
        int k0 = c * 32;
        load_pair(AhiG, AloG, m0, base + SM_A_HI, base + SM_A_LO, k0);
        load_pair(BhiG, BloG, n0, base + SM_B_HI, base + SM_B_LO, k0);
    };

    // ---- per-lane ldmatrix bases -------------------------------------------
    int aRow = (wid & 1) * 64 + ((lane >> 3) & 1) * 8 + (lane & 7);
    int aCol = (lane >> 4) * 16;
    int bRow = (wid >> 1) * 32 + (lane >> 4) * 8 + (lane & 7);
    int bCol = ((lane >> 3) & 1) * 16;

    load_chunk(0, 0);
    CP_COMMIT();

    for (int c = 0; c < nch; ++c) {
        int s = c & 1;
        if (c + 1 < nch) {
            load_chunk(c + 1, s ^ 1);
            CP_COMMIT();
            CP_WAIT(1);                 // chunk c complete, c+1 in flight
        } else {
            CP_WAIT(0);
        }
        __syncthreads();

        uint32_t aHiB = sb + s * STAGE_B + SM_A_HI + aRow * STRIDE + aCol;
        uint32_t aLoB = aHiB + (SM_A_LO - SM_A_HI);
        uint32_t bHiB = sb + s * STAGE_B + SM_B_HI + bRow * STRIDE + bCol;
        uint32_t bLoB = bHiB + (SM_B_LO - SM_B_HI);

#pragma unroll
        for (int ks = 0; ks < 2; ++ks) {
            int kso = ks * 32;
            uint32_t ah[4][4], al[4][4], bh[4][2], bl[4][2];
#pragma unroll
            for (int mi = 0; mi < 4; ++mi) {
                ldmx4(ah[mi], aHiB + mi * (16 * STRIDE) + kso);
                ldmx4(al[mi], aLoB + mi * (16 * STRIDE) + kso);
            }
#pragma unroll
            for (int jj = 0; jj < 2; ++jj) {
                uint32_t t4[4];
                ldmx4(t4, bHiB + jj * (16 * STRIDE) + kso);
                bh[2 * jj][0] = t4[0]; bh[2 * jj][1] = t4[1];
                bh[2 * jj + 1][0] = t4[2]; bh[2 * jj + 1][1] = t4[3];
                ldmx4(t4, bLoB + jj * (16 * STRIDE) + kso);
                bl[2 * jj][0] = t4[0]; bl[2 * jj][1] = t4[1];
                bl[2 * jj + 1][0] = t4[2]; bl[2 * jj + 1][1] = t4[3];
            }
            // term-major: consecutive MMAs hit different accumulators
#pragma unroll
            for (int mi = 0; mi < 4; ++mi)
#pragma unroll
                for (int ni = 0; ni < 4; ++ni)
                    mma16816(acc[mi][ni], ah[mi], bh[ni]);
#pragma unroll
            for (int mi = 0; mi < 4; ++mi)
#pragma unroll
                for (int ni = 0; ni < 4; ++ni)
                    mma16816(acc[mi][ni], ah[mi], bl[ni]);
#pragma unroll
            for (int mi = 0; mi < 4; ++mi)
#pragma unroll
                for (int ni = 0; ni < 4; ++ni)
                    mma16816(acc[mi][ni], al[mi], bh[ni]);
        }
        __syncthreads();
    }

    // ---- epilogue -----------------------------------------------------------
    int mwb = m0 + (wid & 1) * 64;
    int nwb = n0 + (wid >> 1) * 32;
    int mr = lane >> 2, nc = (lane & 3) * 2;
#pragma unroll
    for (int mi = 0; mi < 4; ++mi) {
#pragma unroll
        for (int ni = 0; ni < 4; ++ni) {
            int n = nwb + ni * 8 + nc;
#pragma unroll
            for (int half = 0; half < 2; ++half) {
                int m = mwb + mi * 16 + mr + half * 8;
                float v0 = acc[mi][ni][half * 2 + 0];
                float v1 = acc[mi][ni][half * 2 + 1];
                if (MODE == 0) {
                    float tb = bias[m];
                    float2 rv = *(const float2*)(Res + (size_t)m * 512 + n);
                    v0 += tb + rv.x; v1 += tb + rv.y;
                    *(float2*)(OutF + (size_t)m * 512 + n) = make_float2(v0, v1);
                } else if (MODE == 1) {
                    float2 bb = *(const float2*)(bias + n);
                    float t0 = v0 + bb.x, t1 = v1 + bb.y;
                    float h0 = 0.5f * t0 * (1.0f + erff(t0 * 0.70710678118654752f));
                    float h1 = 0.5f * t1 * (1.0f + erff(t1 * 0.70710678118654752f));
                    __nv_bfloat16 hh0 = __float2bfloat16(h0);
                    __nv_bfloat16 hh1 = __float2bfloat16(h1);
                    __nv_bfloat16 ll0 = __float2bfloat16(h0 - __bfloat162float(hh0));
                    __nv_bfloat16 ll1 = __float2bfloat16(h1 - __bfloat162float(hh1));
                    uint32_t hw = (uint32_t)__bfloat16_as_ushort(hh0) |
                                  ((uint32_t)__bfloat16_as_ushort(hh1) << 16);
                    uint32_t lw = (uint32_t)__bfloat16_as_ushort(ll0) |
                                  ((uint32_t)__bfloat16_as_ushort(ll1) << 16);
                    *(uint32_t*)(OutHi + (size_t)m * 512 + n) = hw;
                    *(uint32_t*)(OutLo + (size_t)m * 512 + n) = lw;
                } else {
                    float2 bb = *(const float2*)(bias + n);
                    float2 rv = *(const float2*)(Res + (size_t)m * 512 + n);
                    v0 += bb.x + rv.x; v1 += bb.y + rv.y;
                    *(float2*)(OutF + (size_t)m * 512 + n) = make_float2(v0, v1);
                }
            }
        }
    }
}

// ---------------------------------------------------------------------------
// Weight pre-split: fp32 -> bf16 (hi, lo); z=0 applies tril mask to Mtri.
// ---------------------------------------------------------------------------
__global__ void split_w(const float* __restrict__ Mt, const float* __restrict__ w1,
                        const float* __restrict__ w2) {
    int idx = blockIdx.x * 256 + threadIdx.x;
    int z = blockIdx.y;
    float v;
    __nv_bfloat16 *H, *L;
    if (z == 0) {
        int i = idx >> 9, j = idx & 511;
        v = (j <= i) ? Mt[idx] : 0.f;
        H = g_mt_hi; L = g_mt_lo;
    } else if (z == 1) {
        v = w1[idx]; H = g_w1_hi; L = g_w1_lo;
    } else {
        v = w2[idx]; H = g_w2_hi; L = g_w2_lo;
    }
    __nv_bfloat16 h = __float2bfloat16(v);
    H[idx] = h;
    L[idx] = __float2bfloat16(v - __bfloat162float(h));
}

// ---------------------------------------------------------------------------
// Per-batch stats, split 16 ways (deterministic two-pass).
// ---------------------------------------------------------------------------
__global__ void stats_part(const float* __restrict__ x, float* __restrict__ part) {
    int b = blockIdx.y, slice = blockIdx.x;
    const float4* p = (const float4*)(x + (size_t)b * NTC) + (size_t)slice * 4096;
    float s = 0.f, s2 = 0.f;
    for (int i = threadIdx.x; i < 4096; i += 256) {
        float4 v = p[i];
        s  += v.x + v.y + v.z + v.w;
        s2 += v.x * v.x + v.y * v.y + v.z * v.z + v.w * v.w;
    }
    __shared__ float sh[256], sh2[256];
    sh[threadIdx.x] = s; sh2[threadIdx.x] = s2;
    __syncthreads();
    for (int o = 128; o > 0; o >>= 1) {
        if (threadIdx.x < o) {
            sh[threadIdx.x] += sh[threadIdx.x + o];
            sh2[threadIdx.x] += sh2[threadIdx.x + o];
        }
        __syncthreads();
    }
    if (threadIdx.x == 0) {
        part[(b * 16 + slice) * 2 + 0] = sh[0];
        part[(b * 16 + slice) * 2 + 1] = sh2[0];
    }
}
__global__ void stats_fin(const float* __restrict__ part, float* __restrict__ mu,
                          float* __restrict__ rs) {
    int b = threadIdx.x;
    float s = 0.f, s2 = 0.f;
    for (int i = 0; i < 16; ++i) {
        s  += part[(b * 16 + i) * 2 + 0];
        s2 += part[(b * 16 + i) * 2 + 1];
    }
    float m = s / (float)NTC;
    float var = s2 / (float)NTC - m * m;
    mu[b] = m;
    rs[b] = rsqrtf(var + 1e-5f);
}

// ---------------------------------------------------------------------------
// LN1 + transpose + bf16 hi/lo split: xt{hi,lo}[b][c][t]
// ---------------------------------------------------------------------------
__global__ void ln1t(const float* __restrict__ x, const float* __restrict__ w,
                     const float* __restrict__ bias, const float* __restrict__ mu,
                     const float* __restrict__ rs,
                     __nv_bfloat16* __restrict__ xthi,
                     __nv_bfloat16* __restrict__ xtlo) {
    __shared__ float tile[32][33];
    int b = blockIdx.z;
    int t0 = blockIdx.x * 32, c0 = blockIdx.y * 32;
    float m = mu[b], r = rs[b];
    int tx = threadIdx.x, ty = threadIdx.y;
#pragma unroll
    for (int k = 0; k < 4; ++k) {
        int t = t0 + ty + k * 8, c = c0 + tx;
        size_t idx = (size_t)t * C_ + c;
        tile[ty + k * 8][tx] = (x[(size_t)b * NTC + idx] - m) * r * w[idx] + bias[idx];
    }
    __syncthreads();
#pragma unroll
    for (int k = 0; k < 4; ++k) {
        int c = c0 + ty + k * 8, t = t0 + tx;
        float v = tile[tx][ty + k * 8];
        __nv_bfloat16 h = __float2bfloat16(v);
        size_t o = (size_t)b * NTC + (size_t)c * T_ + t;
        xthi[o] = h;
        xtlo[o] = __float2bfloat16(v - __bfloat162float(h));
    }
}

// ---------------------------------------------------------------------------
// LN2 apply: fp32 out (residual) + bf16 hi/lo split out.
// ---------------------------------------------------------------------------
__global__ void ln_apply2(const float* __restrict__ x, const float* __restrict__ w,
                          const float* __restrict__ bias, const float* __restrict__ mu,
                          const float* __restrict__ rs, float* __restrict__ out,
                          __nv_bfloat16* __restrict__ ohi,
                          __nv_bfloat16* __restrict__ olo) {
    int b = blockIdx.y;
    int idx = blockIdx.x * blockDim.x + threadIdx.x;
    float m = mu[b], r = rs[b];
    float4 xv = ((const float4*)(x + (size_t)b * NTC))[idx];
    float4 wv = ((const float4*)w)[idx];
    float4 bv = ((const float4*)bias)[idx];
    float o[4];
    o[0] = (xv.x - m) * r * wv.x + bv.x;
    o[1] = (xv.y - m) * r * wv.y + bv.y;
    o[2] = (xv.z - m) * r * wv.z + bv.z;
    o[3] = (xv.w - m) * r * wv.w + bv.w;
    ((float4*)(out + (size_t)b * NTC))[idx] = make_float4(o[0], o[1], o[2], o[3]);
    uint32_t hw[2], lw[2];
#pragma unroll
    for (int e = 0; e < 2; ++e) {
        __nv_bfloat16 h0 = __float2bfloat16(o[2 * e]);
        __nv_bfloat16 h1 = __float2bfloat16(o[2 * e + 1]);
        __nv_bfloat16 l0 = __float2bfloat16(o[2 * e] - __bfloat162float(h0));
        __nv_bfloat16 l1 = __float2bfloat16(o[2 * e + 1] - __bfloat162float(h1));
        hw[e] = (uint32_t)__bfloat16_as_ushort(h0) |
                ((uint32_t)__bfloat16_as_ushort(h1) << 16);
        lw[e] = (uint32_t)__bfloat16_as_ushort(l0) |
                ((uint32_t)__bfloat16_as_ushort(l1) << 16);
    }
    ((uint2*)(ohi + (size_t)b * NTC))[idx] = make_uint2(hw[0], hw[1]);
    ((uint2*)(olo + (size_t)b * NTC))[idx] = make_uint2(lw[0], lw[1]);
}

// ---------------------------------------------------------------------------
extern "C" void kernel_launch(void* const* d_in, const int* in_sizes, int n_in,
                              void* d_out, int out_size) {
    const float* inputs = (const float*)d_in[0];
    const float* ln1w   = (const float*)d_in[1];
    const float* ln1b   = (const float*)d_in[2];
    const float* ln2w   = (const float*)d_in[3];
    const float* ln2b   = (const float*)d_in[4];
    const float* triM   = (const float*)d_in[5];
    const float* trib   = (const float*)d_in[6];
    const float* d1w    = (const float*)d_in[7];
    const float* d1b    = (const float*)d_in[8];
    const float* d2w    = (const float*)d_in[9];
    const float* d2b    = (const float*)d_in[10];
    float* out = (float*)d_out;

    float *Ybuf, *X2buf, *part, *stats;
    __nv_bfloat16 *x1th, *x1tl, *x2h, *x2l, *hh, *hl;
    __nv_bfloat16 *mth, *mtl, *w1h, *w1l, *w2h, *w2l;
    cudaGetSymbolAddress((void**)&Ybuf,  g_Y);
    cudaGetSymbolAddress((void**)&X2buf, g_X2);
    cudaGetSymbolAddress((void**)&part,  g_part);
    cudaGetSymbolAddress((void**)&stats, g_stats);
    cudaGetSymbolAddress((void**)&x1th, g_x1t_hi);
    cudaGetSymbolAddress((void**)&x1tl, g_x1t_lo);
    cudaGetSymbolAddress((void**)&x2h,  g_x2_hi);
    cudaGetSymbolAddress((void**)&x2l,  g_x2_lo);
    cudaGetSymbolAddress((void**)&hh,   g_h_hi);
    cudaGetSymbolAddress((void**)&hl,   g_h_lo);
    cudaGetSymbolAddress((void**)&mth, g_mt_hi);
    cudaGetSymbolAddress((void**)&mtl, g_mt_lo);
    cudaGetSymbolAddress((void**)&w1h, g_w1_hi);
    cudaGetSymbolAddress((void**)&w1l, g_w1_lo);
    cudaGetSymbolAddress((void**)&w2h, g_w2_hi);
    cudaGetSymbolAddress((void**)&w2l, g_w2_lo);
    float* mu1 = stats;
    float* rs1 = stats + B_;
    float* mu2 = stats + 2 * B_;
    float* rs2 = stats + 3 * B_;

    cudaFuncSetAttribute(gemm_mma<0>,
                         cudaFuncAttributeMaxDynamicSharedMemorySize, SMEM_GEMM_BYTES);
    cudaFuncSetAttribute(gemm_mma<1>,
                         cudaFuncAttributeMaxDynamicSharedMemorySize, SMEM_GEMM_BYTES);
    cudaFuncSetAttribute(gemm_mma<2>,
                         cudaFuncAttributeMaxDynamicSharedMemorySize, SMEM_GEMM_BYTES);

    // 0) pre-split weights (tril-masked Mtri, d1_w, d2_w)
    split_w<<<dim3(1024, 3), 256>>>(triM, d1w, d2w);

    // 1) stats of inputs
    stats_part<<<dim3(16, B_), 256>>>(inputs, part);
    stats_fin<<<1, B_>>>(part, mu1, rs1);

    // 2) X1T hi/lo = split(transpose(LN1(inputs)))
    ln1t<<<dim3(T_ / 32, C_ / 32, B_), dim3(32, 8)>>>(inputs, ln1w, ln1b, mu1, rs1,
                                                       x1th, x1tl);

    // 3) Y = tril(M) @ X1 + tri_b + inputs
    gemm_mma<0><<<dim3(4, 4, B_), 256, SMEM_GEMM_BYTES>>>(
        mth, mtl, x1th, x1tl, trib, inputs, Ybuf, nullptr, nullptr,
        0, (size_t)NTC, (size_t)NTC);

    // 4) stats of Y
    stats_part<<<dim3(16, B_), 256>>>(Ybuf, part);
    stats_fin<<<1, B_>>>(part, mu2, rs2);

    // 5) X2 = LN2(Y)  (fp32 + bf16 hi/lo)
    ln_apply2<<<dim3(NTC / 4 / 256, B_), 256>>>(Ybuf, ln2w, ln2b, mu2, rs2,
                                                X2buf, x2h, x2l);

    // 6) H hi/lo = split(gelu(X2 @ d1_w^T + d1_b))
    gemm_mma<1><<<dim3(4, 256, 1), 256, SMEM_GEMM_BYTES>>>(
        x2h, x2l, w1h, w1l, d1b, nullptr, nullptr, hh, hl, 0, 0, 0);

    // 7) out = X2 + H @ d2_w^T + d2_b
    gemm_mma<2><<<dim3(4, 256, 1), 256, SMEM_GEMM_BYTES>>>(
        hh, hl, w2h, w2l, d2b, X2buf, out, nullptr, nullptr, 0, 0, 0);
}

// round 14
// speedup vs baseline: 2.3540x; 1.5074x over previous
#include <cuda_runtime.h>
#include <cuda_bf16.h>
#include <cuda_fp16.h>
#include <math.h>
#include <stdint.h>

#define B_  64
#define T_  512
#define C_  512
#define NTC (T_ * C_)
#define TOT (B_ * T_ * C_)

// ---------------- scratch (__device__ globals; no allocation allowed) -------
__device__ float g_Y[TOT];       // tri-mix output (fp32, LN2 input)
__device__ float g_X2[TOT];      // LN2 output fp32 (residual for final GEMM)
__device__ float g_part[B_ * 16 * 2];
__device__ float g_stats[4 * B_];
// tri path: 3-term bf16 split operands
__device__ __align__(16) __nv_bfloat16 g_x1t_hi[TOT], g_x1t_lo[TOT];  // LN1^T
__device__ __align__(16) __nv_bfloat16 g_mt_hi[T_ * T_], g_mt_lo[T_ * T_];
// MLP path: single-term fp16 operands
__device__ __align__(16) __half g_x2f[TOT];       // LN2 out fp16
__device__ __align__(16) __half g_hf[TOT];        // gelu out fp16
__device__ __align__(16) __half g_w1f[C_ * C_], g_w2f[C_ * C_];

// ---------------- PTX helpers (sm_80-class: valid on compute_103) ----------
__device__ __forceinline__ uint32_t smem_u32(const void* p) {
    uint32_t a;
    asm("{ .reg .u64 t; cvta.to.shared.u64 t, %1; cvt.u32.u64 %0, t; }"
        : "=r"(a) : "l"(p));
    return a;
}
__device__ __forceinline__ void ldmx4(uint32_t* r, uint32_t a) {
    asm volatile("ldmatrix.sync.aligned.m8n8.x4.shared.b16 {%0,%1,%2,%3}, [%4];"
                 : "=r"(r[0]), "=r"(r[1]), "=r"(r[2]), "=r"(r[3]) : "r"(a));
}
__device__ __forceinline__ void mma_bf16(float* c, const uint32_t* a, const uint32_t* b) {
    asm volatile(
        "mma.sync.aligned.m16n8k16.row.col.f32.bf16.bf16.f32 "
        "{%0,%1,%2,%3}, {%4,%5,%6,%7}, {%8,%9}, {%0,%1,%2,%3};"
        : "+f"(c[0]), "+f"(c[1]), "+f"(c[2]), "+f"(c[3])
        : "r"(a[0]), "r"(a[1]), "r"(a[2]), "r"(a[3]), "r"(b[0]), "r"(b[1]));
}
__device__ __forceinline__ void mma_f16(float* c, const uint32_t* a, const uint32_t* b) {
    asm volatile(
        "mma.sync.aligned.m16n8k16.row.col.f32.f16.f16.f32 "
        "{%0,%1,%2,%3}, {%4,%5,%6,%7}, {%8,%9}, {%0,%1,%2,%3};"
        : "+f"(c[0]), "+f"(c[1]), "+f"(c[2]), "+f"(c[3])
        : "r"(a[0]), "r"(a[1]), "r"(a[2]), "r"(a[3]), "r"(b[0]), "r"(b[1]));
}
__device__ __forceinline__ void cp16(uint32_t sdst, const void* gsrc) {
    asm volatile("cp.async.cg.shared.global [%0], [%1], 16;"
                 :: "r"(sdst), "l"(gsrc));
}
#define CP_COMMIT() asm volatile("cp.async.commit_group;" ::: "memory")
#define CP_WAIT(n)  asm volatile("cp.async.wait_group %0;" :: "n"(n) : "memory")

// smem tile: 128 rows x 32 elems(b16) = 64B, padded to 80B/row
#define STRIDE   80
#define TILE_B   (128 * STRIDE)          // 10240

// ============ tri GEMM (3-term bf16): 4 tiles/stage ========================
#define T3_A_HI  0
#define T3_A_LO  (1 * TILE_B)
#define T3_B_HI  (2 * TILE_B)
#define T3_B_LO  (3 * TILE_B)
#define T3_STAGE (4 * TILE_B)            // 40960
#define SMEM_TRI (2 * T3_STAGE)          // 81920

// Y[b,m,n] = sum_{k<=diag} Mtri[m,k]*X1T[b,n,k] + trib[m] + inputs[b,m,n]
__global__ __launch_bounds__(256, 1)
void trigemm(const __nv_bfloat16* __restrict__ AhiG, const __nv_bfloat16* __restrict__ AloG,
             const __nv_bfloat16* BhiGall, const __nv_bfloat16* BloGall,
             const float* __restrict__ bias, const float* ResAll, float* OutAll) {
    extern __shared__ char smem[];
    const int Kd = 512;
    int tid = threadIdx.x, wid = tid >> 5, lane = tid & 31;
    int n0 = blockIdx.x * 128, m0 = blockIdx.y * 128;
    size_t bz = blockIdx.z;
    const __nv_bfloat16* BhiG = BhiGall + bz * NTC;
    const __nv_bfloat16* BloG = BloGall + bz * NTC;
    const float* Res = ResAll + bz * NTC;
    float* OutF = OutAll + bz * NTC;

    uint32_t sb = smem_u32(smem);
    float acc[4][4][4];
#pragma unroll
    for (int i = 0; i < 4; i++)
#pragma unroll
        for (int j = 0; j < 4; j++)
#pragma unroll
            for (int e = 0; e < 4; e++) acc[i][j][e] = 0.f;

    int nch = (m0 + 128) / 32;          // K truncated at diagonal tile

    auto load_pair = [&](const __nv_bfloat16* Hg, const __nv_bfloat16* Lg,
                         int row0, uint32_t dhi, uint32_t dlo, int k0) {
#pragma unroll
        for (int it = 0; it < 2; ++it) {
            int seg = tid + it * 256;
            int r = seg >> 2, c8 = (seg & 3) * 8;
            size_t go = (size_t)(row0 + r) * Kd + k0 + c8;
            uint32_t off = (uint32_t)(r * STRIDE + c8 * 2);
            cp16(dhi + off, Hg + go);
            cp16(dlo + off, Lg + go);
        }
    };
    auto load_chunk = [&](int c, int s) {
        uint32_t base = sb + s * T3_STAGE;
        int k0 = c * 32;
        load_pair(AhiG, AloG, m0, base + T3_A_HI, base + T3_A_LO, k0);
        load_pair(BhiG, BloG, n0, base + T3_B_HI, base + T3_B_LO, k0);
    };

    int aRow = (wid & 1) * 64 + ((lane >> 3) & 1) * 8 + (lane & 7);
    int aCol = (lane >> 4) * 16;
    int bRow = (wid >> 1) * 32 + (lane >> 4) * 8 + (lane & 7);
    int bCol = ((lane >> 3) & 1) * 16;

    load_chunk(0, 0);
    CP_COMMIT();

    for (int c = 0; c < nch; ++c) {
        int s = c & 1;
        if (c + 1 < nch) { load_chunk(c + 1, s ^ 1); CP_COMMIT(); CP_WAIT(1); }
        else             { CP_WAIT(0); }
        __syncthreads();

        uint32_t aHiB = sb + s * T3_STAGE + T3_A_HI + aRow * STRIDE + aCol;
        uint32_t aLoB = aHiB + TILE_B;
        uint32_t bHiB = sb + s * T3_STAGE + T3_B_HI + bRow * STRIDE + bCol;
        uint32_t bLoB = bHiB + TILE_B;

#pragma unroll
        for (int ks = 0; ks < 2; ++ks) {
            int kso = ks * 32;
            uint32_t ah[4][4], al[4][4], bh[4][2], bl[4][2];
#pragma unroll
            for (int mi = 0; mi < 4; ++mi) {
                ldmx4(ah[mi], aHiB + mi * (16 * STRIDE) + kso);
                ldmx4(al[mi], aLoB + mi * (16 * STRIDE) + kso);
            }
#pragma unroll
            for (int jj = 0; jj < 2; ++jj) {
                uint32_t t4[4];
                ldmx4(t4, bHiB + jj * (16 * STRIDE) + kso);
                bh[2 * jj][0] = t4[0]; bh[2 * jj][1] = t4[1];
                bh[2 * jj + 1][0] = t4[2]; bh[2 * jj + 1][1] = t4[3];
                ldmx4(t4, bLoB + jj * (16 * STRIDE) + kso);
                bl[2 * jj][0] = t4[0]; bl[2 * jj][1] = t4[1];
                bl[2 * jj + 1][0] = t4[2]; bl[2 * jj + 1][1] = t4[3];
            }
#pragma unroll
            for (int mi = 0; mi < 4; ++mi)
#pragma unroll
                for (int ni = 0; ni < 4; ++ni)
                    mma_bf16(acc[mi][ni], ah[mi], bh[ni]);
#pragma unroll
            for (int mi = 0; mi < 4; ++mi)
#pragma unroll
                for (int ni = 0; ni < 4; ++ni)
                    mma_bf16(acc[mi][ni], ah[mi], bl[ni]);
#pragma unroll
            for (int mi = 0; mi < 4; ++mi)
#pragma unroll
                for (int ni = 0; ni < 4; ++ni)
                    mma_bf16(acc[mi][ni], al[mi], bh[ni]);
        }
        __syncthreads();
    }

    int mwb = m0 + (wid & 1) * 64;
    int nwb = n0 + (wid >> 1) * 32;
    int mr = lane >> 2, nc = (lane & 3) * 2;
#pragma unroll
    for (int mi = 0; mi < 4; ++mi)
#pragma unroll
        for (int ni = 0; ni < 4; ++ni) {
            int n = nwb + ni * 8 + nc;
#pragma unroll
            for (int half = 0; half < 2; ++half) {
                int m = mwb + mi * 16 + mr + half * 8;
                float tb = bias[m];
                float2 rv = *(const float2*)(Res + (size_t)m * 512 + n);
                float v0 = acc[mi][ni][half * 2 + 0] + tb + rv.x;
                float v1 = acc[mi][ni][half * 2 + 1] + tb + rv.y;
                *(float2*)(OutF + (size_t)m * 512 + n) = make_float2(v0, v1);
            }
        }
}

// ============ dense MLP GEMM (1-term fp16): 2 tiles/stage ===================
#define F1_A     0
#define F1_B     TILE_B
#define F1_STAGE (2 * TILE_B)            // 20480
#define SMEM_F16 (2 * F1_STAGE)          // 40960

// MODE 1: OutH = fp16(gelu(acc + bias[n]))
// MODE 2: OutF = acc + bias[n] + Res[m,n]
template <int MODE>
__global__ __launch_bounds__(256, 1)
void gemm_f16(const __half* __restrict__ AG, const __half* __restrict__ BG,
              const float* __restrict__ bias, const float* __restrict__ Res,
              float* __restrict__ OutF, __half* __restrict__ OutH) {
    extern __shared__ char smem[];
    const int Kd = 512;
    int tid = threadIdx.x, wid = tid >> 5, lane = tid & 31;
    int n0 = blockIdx.x * 128, m0 = blockIdx.y * 128;

    uint32_t sb = smem_u32(smem);
    float acc[4][4][4];
#pragma unroll
    for (int i = 0; i < 4; i++)
#pragma unroll
        for (int j = 0; j < 4; j++)
#pragma unroll
            for (int e = 0; e < 4; e++) acc[i][j][e] = 0.f;

    auto load_tile = [&](const __half* G, int row0, uint32_t dst, int k0) {
#pragma unroll
        for (int it = 0; it < 2; ++it) {
            int seg = tid + it * 256;
            int r = seg >> 2, c8 = (seg & 3) * 8;
            size_t go = (size_t)(row0 + r) * Kd + k0 + c8;
            cp16(dst + (uint32_t)(r * STRIDE + c8 * 2), G + go);
        }
    };
    auto load_chunk = [&](int c, int s) {
        uint32_t base = sb + s * F1_STAGE;
        int k0 = c * 32;
        load_tile(AG, m0, base + F1_A, k0);
        load_tile(BG, n0, base + F1_B, k0);
    };

    int aRow = (wid & 1) * 64 + ((lane >> 3) & 1) * 8 + (lane & 7);
    int aCol = (lane >> 4) * 16;
    int bRow = (wid >> 1) * 32 + (lane >> 4) * 8 + (lane & 7);
    int bCol = ((lane >> 3) & 1) * 16;

    load_chunk(0, 0);
    CP_COMMIT();

    for (int c = 0; c < 16; ++c) {
        int s = c & 1;
        if (c + 1 < 16) { load_chunk(c + 1, s ^ 1); CP_COMMIT(); CP_WAIT(1); }
        else            { CP_WAIT(0); }
        __syncthreads();

        uint32_t aB = sb + s * F1_STAGE + F1_A + aRow * STRIDE + aCol;
        uint32_t bB = sb + s * F1_STAGE + F1_B + bRow * STRIDE + bCol;

#pragma unroll
        for (int ks = 0; ks < 2; ++ks) {
            int kso = ks * 32;
            uint32_t ah[4][4], bh[4][2];
#pragma unroll
            for (int mi = 0; mi < 4; ++mi)
                ldmx4(ah[mi], aB + mi * (16 * STRIDE) + kso);
#pragma unroll
            for (int jj = 0; jj < 2; ++jj) {
                uint32_t t4[4];
                ldmx4(t4, bB + jj * (16 * STRIDE) + kso);
                bh[2 * jj][0] = t4[0]; bh[2 * jj][1] = t4[1];
                bh[2 * jj + 1][0] = t4[2]; bh[2 * jj + 1][1] = t4[3];
            }
#pragma unroll
            for (int mi = 0; mi < 4; ++mi)
#pragma unroll
                for (int ni = 0; ni < 4; ++ni)
                    mma_f16(acc[mi][ni], ah[mi], bh[ni]);
        }
        __syncthreads();
    }

    int mwb = m0 + (wid & 1) * 64;
    int nwb = n0 + (wid >> 1) * 32;
    int mr = lane >> 2, nc = (lane & 3) * 2;
#pragma unroll
    for (int mi = 0; mi < 4; ++mi)
#pragma unroll
        for (int ni = 0; ni < 4; ++ni) {
            int n = nwb + ni * 8 + nc;
#pragma unroll
            for (int half = 0; half < 2; ++half) {
                int m = mwb + mi * 16 + mr + half * 8;
                float v0 = acc[mi][ni][half * 2 + 0];
                float v1 = acc[mi][ni][half * 2 + 1];
                float2 bb = *(const float2*)(bias + n);
                if (MODE == 1) {
                    float t0 = v0 + bb.x, t1 = v1 + bb.y;
                    float h0 = 0.5f * t0 * (1.0f + erff(t0 * 0.70710678118654752f));
                    float h1 = 0.5f * t1 * (1.0f + erff(t1 * 0.70710678118654752f));
                    *(__half2*)(OutH + (size_t)m * 512 + n) = __floats2half2_rn(h0, h1);
                } else {
                    float2 rv = *(const float2*)(Res + (size_t)m * 512 + n);
                    v0 += bb.x + rv.x; v1 += bb.y + rv.y;
                    *(float2*)(OutF + (size_t)m * 512 + n) = make_float2(v0, v1);
                }
            }
        }
}

// ---------------------------------------------------------------------------
// Weight prep: z=0 Mtri -> tril-masked bf16 hi/lo; z=1 w1 -> fp16; z=2 w2 -> fp16
// ---------------------------------------------------------------------------
__global__ void split_w(const float* __restrict__ Mt, const float* __restrict__ w1,
                        const float* __restrict__ w2) {
    int idx = blockIdx.x * 256 + threadIdx.x;
    int z = blockIdx.y;
    if (z == 0) {
        int i = idx >> 9, j = idx & 511;
        float v = (j <= i) ? Mt[idx] : 0.f;
        __nv_bfloat16 h = __float2bfloat16(v);
        g_mt_hi[idx] = h;
        g_mt_lo[idx] = __float2bfloat16(v - __bfloat162float(h));
    } else if (z == 1) {
        g_w1f[idx] = __float2half(w1[idx]);
    } else {
        g_w2f[idx] = __float2half(w2[idx]);
    }
}

// ---------------------------------------------------------------------------
// Per-batch stats, split 16 ways (deterministic two-pass).
// ---------------------------------------------------------------------------
__global__ void stats_part(const float* __restrict__ x, float* __restrict__ part) {
    int b = blockIdx.y, slice = blockIdx.x;
    const float4* p = (const float4*)(x + (size_t)b * NTC) + (size_t)slice * 4096;
    float s = 0.f, s2 = 0.f;
    for (int i = threadIdx.x; i < 4096; i += 256) {
        float4 v = p[i];
        s  += v.x + v.y + v.z + v.w;
        s2 += v.x * v.x + v.y * v.y + v.z * v.z + v.w * v.w;
    }
    __shared__ float sh[256], sh2[256];
    sh[threadIdx.x] = s; sh2[threadIdx.x] = s2;
    __syncthreads();
    for (int o = 128; o > 0; o >>= 1) {
        if (threadIdx.x < o) {
            sh[threadIdx.x] += sh[threadIdx.x + o];
            sh2[threadIdx.x] += sh2[threadIdx.x + o];
        }
        __syncthreads();
    }
    if (threadIdx.x == 0) {
        part[(b * 16 + slice) * 2 + 0] = sh[0];
        part[(b * 16 + slice) * 2 + 1] = sh2[0];
    }
}
__global__ void stats_fin(const float* __restrict__ part, float* __restrict__ mu,
                          float* __restrict__ rs) {
    int b = threadIdx.x;
    float s = 0.f, s2 = 0.f;
    for (int i = 0; i < 16; ++i) {
        s  += part[(b * 16 + i) * 2 + 0];
        s2 += part[(b * 16 + i) * 2 + 1];
    }
    float m = s / (float)NTC;
    float var = s2 / (float)NTC - m * m;
    mu[b] = m;
    rs[b] = rsqrtf(var + 1e-5f);
}

// ---------------------------------------------------------------------------
// LN1 + transpose + bf16 hi/lo split
// ---------------------------------------------------------------------------
__global__ void ln1t(const float* __restrict__ x, const float* __restrict__ w,
                     const float* __restrict__ bias, const float* __restrict__ mu,
                     const float* __restrict__ rs,
                     __nv_bfloat16* __restrict__ xthi,
                     __nv_bfloat16* __restrict__ xtlo) {
    __shared__ float tile[32][33];
    int b = blockIdx.z;
    int t0 = blockIdx.x * 32, c0 = blockIdx.y * 32;
    float m = mu[b], r = rs[b];
    int tx = threadIdx.x, ty = threadIdx.y;
#pragma unroll
    for (int k = 0; k < 4; ++k) {
        int t = t0 + ty + k * 8, c = c0 + tx;
        size_t idx = (size_t)t * C_ + c;
        tile[ty + k * 8][tx] = (x[(size_t)b * NTC + idx] - m) * r * w[idx] + bias[idx];
    }
    __syncthreads();
#pragma unroll
    for (int k = 0; k < 4; ++k) {
        int c = c0 + ty + k * 8, t = t0 + tx;
        float v = tile[tx][ty + k * 8];
        __nv_bfloat16 h = __float2bfloat16(v);
        size_t o = (size_t)b * NTC + (size_t)c * T_ + t;
        xthi[o] = h;
        xtlo[o] = __float2bfloat16(v - __bfloat162float(h));
    }
}

// ---------------------------------------------------------------------------
// LN2 apply: fp32 out (residual) + fp16 out (GEMM1 operand).
// ---------------------------------------------------------------------------
__global__ void ln_apply2(const float* __restrict__ x, const float* __restrict__ w,
                          const float* __restrict__ bias, const float* __restrict__ mu,
                          const float* __restrict__ rs, float* __restrict__ out,
                          __half* __restrict__ outh) {
    int b = blockIdx.y;
    int idx = blockIdx.x * blockDim.x + threadIdx.x;
    float m = mu[b], r = rs[b];
    float4 xv = ((const float4*)(x + (size_t)b * NTC))[idx];
    float4 wv = ((const float4*)w)[idx];
    float4 bv = ((const float4*)bias)[idx];
    float o0 = (xv.x - m) * r * wv.x + bv.x;
    float o1 = (xv.y - m) * r * wv.y + bv.y;
    float o2 = (xv.z - m) * r * wv.z + bv.z;
    float o3 = (xv.w - m) * r * wv.w + bv.w;
    ((float4*)(out + (size_t)b * NTC))[idx] = make_float4(o0, o1, o2, o3);
    __half2 h01 = __floats2half2_rn(o0, o1);
    __half2 h23 = __floats2half2_rn(o2, o3);
    uint32_t u01, u23;
    memcpy(&u01, &h01, 4);
    memcpy(&u23, &h23, 4);
    ((uint2*)(outh + (size_t)b * NTC))[idx] = make_uint2(u01, u23);
}

// ---------------------------------------------------------------------------
extern "C" void kernel_launch(void* const* d_in, const int* in_sizes, int n_in,
                              void* d_out, int out_size) {
    const float* inputs = (const float*)d_in[0];
    const float* ln1w   = (const float*)d_in[1];
    const float* ln1b   = (const float*)d_in[2];
    const float* ln2w   = (const float*)d_in[3];
    const float* ln2b   = (const float*)d_in[4];
    const float* triM   = (const float*)d_in[5];
    const float* trib   = (const float*)d_in[6];
    const float* d1w    = (const float*)d_in[7];
    const float* d1b    = (const float*)d_in[8];
    const float* d2w    = (const float*)d_in[9];
    const float* d2b    = (const float*)d_in[10];
    float* out = (float*)d_out;

    float *Ybuf, *X2buf, *part, *stats;
    __nv_bfloat16 *x1th, *x1tl, *mth, *mtl;
    __half *x2f, *hf, *w1f, *w2f;
    cudaGetSymbolAddress((void**)&Ybuf,  g_Y);
    cudaGetSymbolAddress((void**)&X2buf, g_X2);
    cudaGetSymbolAddress((void**)&part,  g_part);
    cudaGetSymbolAddress((void**)&stats, g_stats);
    cudaGetSymbolAddress((void**)&x1th, g_x1t_hi);
    cudaGetSymbolAddress((void**)&x1tl, g_x1t_lo);
    cudaGetSymbolAddress((void**)&mth, g_mt_hi);
    cudaGetSymbolAddress((void**)&mtl, g_mt_lo);
    cudaGetSymbolAddress((void**)&x2f, g_x2f);
    cudaGetSymbolAddress((void**)&hf,  g_hf);
    cudaGetSymbolAddress((void**)&w1f, g_w1f);
    cudaGetSymbolAddress((void**)&w2f, g_w2f);
    float* mu1 = stats;
    float* rs1 = stats + B_;
    float* mu2 = stats + 2 * B_;
    float* rs2 = stats + 3 * B_;

    cudaFuncSetAttribute(trigemm,
                         cudaFuncAttributeMaxDynamicSharedMemorySize, SMEM_TRI);
    cudaFuncSetAttribute(gemm_f16<1>,
                         cudaFuncAttributeMaxDynamicSharedMemorySize, SMEM_F16);
    cudaFuncSetAttribute(gemm_f16<2>,
                         cudaFuncAttributeMaxDynamicSharedMemorySize, SMEM_F16);

    // 0) weight prep
    split_w<<<dim3(1024, 3), 256>>>(triM, d1w, d2w);

    // 1) stats of inputs
    stats_part<<<dim3(16, B_), 256>>>(inputs, part);
    stats_fin<<<1, B_>>>(part, mu1, rs1);

    // 2) X1T hi/lo = split(transpose(LN1(inputs)))
    ln1t<<<dim3(T_ / 32, C_ / 32, B_), dim3(32, 8)>>>(inputs, ln1w, ln1b, mu1, rs1,
                                                       x1th, x1tl);

    // 3) Y = tril(M) @ X1 + tri_b + inputs   (3-term bf16)
    trigemm<<<dim3(4, 4, B_), 256, SMEM_TRI>>>(mth, mtl, x1th, x1tl,
                                               trib, inputs, Ybuf);

    // 4) stats of Y
    stats_part<<<dim3(16, B_), 256>>>(Ybuf, part);
    stats_fin<<<1, B_>>>(part, mu2, rs2);

    // 5) X2 = LN2(Y)  (fp32 + fp16)
    ln_apply2<<<dim3(NTC / 4 / 256, B_), 256>>>(Ybuf, ln2w, ln2b, mu2, rs2,
                                                X2buf, x2f);

    // 6) H = fp16(gelu(X2 @ d1_w^T + d1_b))   (1-term fp16)
    gemm_f16<1><<<dim3(4, 256), 256, SMEM_F16>>>(x2f, w1f, d1b, nullptr,
                                                 nullptr, hf);

    // 7) out = X2 + H @ d2_w^T + d2_b          (1-term fp16)
    gemm_f16<2><<<dim3(4, 256), 256, SMEM_F16>>>(hf, w2f, d2b, X2buf,
                                                 out, nullptr);
}

// round 15
// speedup vs baseline: 3.2359x; 1.3746x over previous
#include <cuda_runtime.h>
#include <cuda_fp16.h>
#include <math.h>
#include <stdint.h>

#define B_  64
#define T_  512
#define C_  512
#define NTC (T_ * C_)
#define TOT (B_ * T_ * C_)

// ---------------- scratch (__device__ globals; no allocation allowed) -------
__device__ float g_Y[TOT];       // tri-mix output (fp32, LN2 input)
__device__ float g_X2[TOT];      // LN2 output fp32 (residual for final GEMM)
__device__ float g_part[B_ * 16 * 2];
__device__ float g_stats[4 * B_];
// fp16 operands
__device__ __align__(16) __half g_x1tf[TOT];      // LN1^T fp16
__device__ __align__(16) __half g_x2f[TOT];       // LN2 out fp16
__device__ __align__(16) __half g_hf[TOT];        // gelu out fp16
__device__ __align__(16) __half g_mtf[T_ * T_];   // tril-masked Mtri fp16
__device__ __align__(16) __half g_w1f[C_ * C_], g_w2f[C_ * C_];

// ---------------- PTX helpers (sm_80-class: valid on compute_103) ----------
__device__ __forceinline__ uint32_t smem_u32(const void* p) {
    uint32_t a;
    asm("{ .reg .u64 t; cvta.to.shared.u64 t, %1; cvt.u32.u64 %0, t; }"
        : "=r"(a) : "l"(p));
    return a;
}
__device__ __forceinline__ void ldmx4(uint32_t* r, uint32_t a) {
    asm volatile("ldmatrix.sync.aligned.m8n8.x4.shared.b16 {%0,%1,%2,%3}, [%4];"
                 : "=r"(r[0]), "=r"(r[1]), "=r"(r[2]), "=r"(r[3]) : "r"(a));
}
__device__ __forceinline__ void mma_f16(float* c, const uint32_t* a, const uint32_t* b) {
    asm volatile(
        "mma.sync.aligned.m16n8k16.row.col.f32.f16.f16.f32 "
        "{%0,%1,%2,%3}, {%4,%5,%6,%7}, {%8,%9}, {%0,%1,%2,%3};"
        : "+f"(c[0]), "+f"(c[1]), "+f"(c[2]), "+f"(c[3])
        : "r"(a[0]), "r"(a[1]), "r"(a[2]), "r"(a[3]), "r"(b[0]), "r"(b[1]));
}
__device__ __forceinline__ void cp16(uint32_t sdst, const void* gsrc) {
    asm volatile("cp.async.cg.shared.global [%0], [%1], 16;"
                 :: "r"(sdst), "l"(gsrc));
}
#define CP_COMMIT() asm volatile("cp.async.commit_group;" ::: "memory")
#define CP_WAIT(n)  asm volatile("cp.async.wait_group %0;" :: "n"(n) : "memory")

// smem tile: 128 rows x 32 fp16 (64B), padded to 80B/row (conflict-free ldmatrix)
#define STRIDE   80
#define TILE_B   (128 * STRIDE)          // 10240
#define F1_STAGE (2 * TILE_B)            // 20480 (A tile + B tile)
#define SMEM_F16 (2 * F1_STAGE)          // 40960 (double buffered)

// ---------------------------------------------------------------------------
// fp16 mma.sync GEMM: D[m,n] = sum_k A[m,k]*B[n,k], 128x128 tile, BK=32.
// MODE 0: OutF = acc + bias[m] + Res[m,n]   (tri: A=Mtri shared, B batched,
//                                            K truncated at diagonal tile)
// MODE 1: OutH = fp16(gelu(acc + bias[n]))
// MODE 2: OutF = acc + bias[n] + Res[m,n]
// ---------------------------------------------------------------------------
template <int MODE>
__global__ __launch_bounds__(256, 2)
void gemm_f16(const __half* __restrict__ AG, const __half* __restrict__ BGall,
              const float* __restrict__ bias, const float* ResAll,
              float* OutAll, __half* __restrict__ OutH) {
    extern __shared__ char smem[];
    const int Kd = 512;
    int tid = threadIdx.x, wid = tid >> 5, lane = tid & 31;
    int n0 = blockIdx.x * 128, m0 = blockIdx.y * 128;
    size_t bz = blockIdx.z;

    const __half* BG = (MODE == 0) ? (BGall + bz * NTC) : BGall;
    const float* Res = ResAll;
    float* OutF = OutAll;
    if (MODE == 0) { Res = ResAll + bz * NTC; OutF = OutAll + bz * NTC; }

    uint32_t sb = smem_u32(smem);
    float acc[4][4][4];
#pragma unroll
    for (int i = 0; i < 4; i++)
#pragma unroll
        for (int j = 0; j < 4; j++)
#pragma unroll
            for (int e = 0; e < 4; e++) acc[i][j][e] = 0.f;

    int nch = (MODE == 0) ? (m0 + 128) / 32 : 16;

    auto load_tile = [&](const __half* G, int row0, uint32_t dst, int k0) {
#pragma unroll
        for (int it = 0; it < 2; ++it) {
            int seg = tid + it * 256;
            int r = seg >> 2, c8 = (seg & 3) * 8;
            size_t go = (size_t)(row0 + r) * Kd + k0 + c8;
            cp16(dst + (uint32_t)(r * STRIDE + c8 * 2), G + go);
        }
    };
    auto load_chunk = [&](int c, int s) {
        uint32_t base = sb + s * F1_STAGE;
        int k0 = c * 32;
        load_tile(AG, m0, base, k0);
        load_tile(BG, n0, base + TILE_B, k0);
    };

    int aRow = (wid & 1) * 64 + ((lane >> 3) & 1) * 8 + (lane & 7);
    int aCol = (lane >> 4) * 16;
    int bRow = (wid >> 1) * 32 + (lane >> 4) * 8 + (lane & 7);
    int bCol = ((lane >> 3) & 1) * 16;

    load_chunk(0, 0);
    CP_COMMIT();

    for (int c = 0; c < nch; ++c) {
        int s = c & 1;
        if (c + 1 < nch) { load_chunk(c + 1, s ^ 1); CP_COMMIT(); CP_WAIT(1); }
        else             { CP_WAIT(0); }
        __syncthreads();

        uint32_t aB = sb + s * F1_STAGE + aRow * STRIDE + aCol;
        uint32_t bB = sb + s * F1_STAGE + TILE_B + bRow * STRIDE + bCol;

#pragma unroll
        for (int ks = 0; ks < 2; ++ks) {
            int kso = ks * 32;
            uint32_t ah[4][4], bh[4][2];
#pragma unroll
            for (int mi = 0; mi < 4; ++mi)
                ldmx4(ah[mi], aB + mi * (16 * STRIDE) + kso);
#pragma unroll
            for (int jj = 0; jj < 2; ++jj) {
                uint32_t t4[4];
                ldmx4(t4, bB + jj * (16 * STRIDE) + kso);
                bh[2 * jj][0] = t4[0]; bh[2 * jj][1] = t4[1];
                bh[2 * jj + 1][0] = t4[2]; bh[2 * jj + 1][1] = t4[3];
            }
#pragma unroll
            for (int mi = 0; mi < 4; ++mi)
#pragma unroll
                for (int ni = 0; ni < 4; ++ni)
                    mma_f16(acc[mi][ni], ah[mi], bh[ni]);
        }
        __syncthreads();
    }

    int mwb = m0 + (wid & 1) * 64;
    int nwb = n0 + (wid >> 1) * 32;
    int mr = lane >> 2, nc = (lane & 3) * 2;
#pragma unroll
    for (int mi = 0; mi < 4; ++mi)
#pragma unroll
        for (int ni = 0; ni < 4; ++ni) {
            int n = nwb + ni * 8 + nc;
#pragma unroll
            for (int half = 0; half < 2; ++half) {
                int m = mwb + mi * 16 + mr + half * 8;
                float v0 = acc[mi][ni][half * 2 + 0];
                float v1 = acc[mi][ni][half * 2 + 1];
                if (MODE == 0) {
                    float tb = bias[m];
                    float2 rv = *(const float2*)(Res + (size_t)m * 512 + n);
                    v0 += tb + rv.x; v1 += tb + rv.y;
                    *(float2*)(OutF + (size_t)m * 512 + n) = make_float2(v0, v1);
                } else if (MODE == 1) {
                    float2 bb = *(const float2*)(bias + n);
                    float t0 = v0 + bb.x, t1 = v1 + bb.y;
                    float h0 = 0.5f * t0 * (1.0f + erff(t0 * 0.70710678118654752f));
                    float h1 = 0.5f * t1 * (1.0f + erff(t1 * 0.70710678118654752f));
                    *(__half2*)(OutH + (size_t)m * 512 + n) = __floats2half2_rn(h0, h1);
                } else {
                    float2 bb = *(const float2*)(bias + n);
                    float2 rv = *(const float2*)(Res + (size_t)m * 512 + n);
                    v0 += bb.x + rv.x; v1 += bb.y + rv.y;
                    *(float2*)(OutF + (size_t)m * 512 + n) = make_float2(v0, v1);
                }
            }
        }
}

// ---------------------------------------------------------------------------
// Weight prep: z=0 Mtri -> tril-masked fp16; z=1 w1 -> fp16; z=2 w2 -> fp16
// ---------------------------------------------------------------------------
__global__ void split_w(const float* __restrict__ Mt, const float* __restrict__ w1,
                        const float* __restrict__ w2) {
    int idx = blockIdx.x * 256 + threadIdx.x;
    int z = blockIdx.y;
    if (z == 0) {
        int i = idx >> 9, j = idx & 511;
        float v = (j <= i) ? Mt[idx] : 0.f;
        g_mtf[idx] = __float2half(v);
    } else if (z == 1) {
        g_w1f[idx] = __float2half(w1[idx]);
    } else {
        g_w2f[idx] = __float2half(w2[idx]);
    }
}

// ---------------------------------------------------------------------------
// Per-batch stats, split 16 ways (deterministic two-pass).
// ---------------------------------------------------------------------------
__global__ void stats_part(const float* __restrict__ x, float* __restrict__ part) {
    int b = blockIdx.y, slice = blockIdx.x;
    const float4* p = (const float4*)(x + (size_t)b * NTC) + (size_t)slice * 4096;
    float s = 0.f, s2 = 0.f;
    for (int i = threadIdx.x; i < 4096; i += 256) {
        float4 v = p[i];
        s  += v.x + v.y + v.z + v.w;
        s2 += v.x * v.x + v.y * v.y + v.z * v.z + v.w * v.w;
    }
    __shared__ float sh[256], sh2[256];
    sh[threadIdx.x] = s; sh2[threadIdx.x] = s2;
    __syncthreads();
    for (int o = 128; o > 0; o >>= 1) {
        if (threadIdx.x < o) {
            sh[threadIdx.x] += sh[threadIdx.x + o];
            sh2[threadIdx.x] += sh2[threadIdx.x + o];
        }
        __syncthreads();
    }
    if (threadIdx.x == 0) {
        part[(b * 16 + slice) * 2 + 0] = sh[0];
        part[(b * 16 + slice) * 2 + 1] = sh2[0];
    }
}
__global__ void stats_fin(const float* __restrict__ part, float* __restrict__ mu,
                          float* __restrict__ rs) {
    int b = threadIdx.x;
    float s = 0.f, s2 = 0.f;
    for (int i = 0; i < 16; ++i) {
        s  += part[(b * 16 + i) * 2 + 0];
        s2 += part[(b * 16 + i) * 2 + 1];
    }
    float m = s / (float)NTC;
    float var = s2 / (float)NTC - m * m;
    mu[b] = m;
    rs[b] = rsqrtf(var + 1e-5f);
}

// ---------------------------------------------------------------------------
// LN1 + transpose -> fp16: x1tf[b][c][t]
// ---------------------------------------------------------------------------
__global__ void ln1t(const float* __restrict__ x, const float* __restrict__ w,
                     const float* __restrict__ bias, const float* __restrict__ mu,
                     const float* __restrict__ rs, __half* __restrict__ xtf) {
    __shared__ float tile[32][33];
    int b = blockIdx.z;
    int t0 = blockIdx.x * 32, c0 = blockIdx.y * 32;
    float m = mu[b], r = rs[b];
    int tx = threadIdx.x, ty = threadIdx.y;
#pragma unroll
    for (int k = 0; k < 4; ++k) {
        int t = t0 + ty + k * 8, c = c0 + tx;
        size_t idx = (size_t)t * C_ + c;
        tile[ty + k * 8][tx] = (x[(size_t)b * NTC + idx] - m) * r * w[idx] + bias[idx];
    }
    __syncthreads();
#pragma unroll
    for (int k = 0; k < 4; ++k) {
        int c = c0 + ty + k * 8, t = t0 + tx;
        xtf[(size_t)b * NTC + (size_t)c * T_ + t] = __float2half(tile[tx][ty + k * 8]);
    }
}

// ---------------------------------------------------------------------------
// LN2 apply: fp32 out (residual) + fp16 out (GEMM1 operand).
// ---------------------------------------------------------------------------
__global__ void ln_apply2(const float* __restrict__ x, const float* __restrict__ w,
                          const float* __restrict__ bias, const float* __restrict__ mu,
                          const float* __restrict__ rs, float* __restrict__ out,
                          __half* __restrict__ outh) {
    int b = blockIdx.y;
    int idx = blockIdx.x * blockDim.x + threadIdx.x;
    float m = mu[b], r = rs[b];
    float4 xv = ((const float4*)(x + (size_t)b * NTC))[idx];
    float4 wv = ((const float4*)w)[idx];
    float4 bv = ((const float4*)bias)[idx];
    float o0 = (xv.x - m) * r * wv.x + bv.x;
    float o1 = (xv.y - m) * r * wv.y + bv.y;
    float o2 = (xv.z - m) * r * wv.z + bv.z;
    float o3 = (xv.w - m) * r * wv.w + bv.w;
    ((float4*)(out + (size_t)b * NTC))[idx] = make_float4(o0, o1, o2, o3);
    __half2 h01 = __floats2half2_rn(o0, o1);
    __half2 h23 = __floats2half2_rn(o2, o3);
    uint32_t u01, u23;
    memcpy(&u01, &h01, 4);
    memcpy(&u23, &h23, 4);
    ((uint2*)(outh + (size_t)b * NTC))[idx] = make_uint2(u01, u23);
}

// ---------------------------------------------------------------------------
extern "C" void kernel_launch(void* const* d_in, const int* in_sizes, int n_in,
                              void* d_out, int out_size) {
    const float* inputs = (const float*)d_in[0];
    const float* ln1w   = (const float*)d_in[1];
    const float* ln1b   = (const float*)d_in[2];
    const float* ln2w   = (const float*)d_in[3];
    const float* ln2b   = (const float*)d_in[4];
    const float* triM   = (const float*)d_in[5];
    const float* trib   = (const float*)d_in[6];
    const float* d1w    = (const float*)d_in[7];
    const float* d1b    = (const float*)d_in[8];
    const float* d2w    = (const float*)d_in[9];
    const float* d2b    = (const float*)d_in[10];
    float* out = (float*)d_out;

    float *Ybuf, *X2buf, *part, *stats;
    __half *x1tf, *x2f, *hf, *mtf, *w1f, *w2f;
    cudaGetSymbolAddress((void**)&Ybuf,  g_Y);
    cudaGetSymbolAddress((void**)&X2buf, g_X2);
    cudaGetSymbolAddress((void**)&part,  g_part);
    cudaGetSymbolAddress((void**)&stats, g_stats);
    cudaGetSymbolAddress((void**)&x1tf, g_x1tf);
    cudaGetSymbolAddress((void**)&x2f,  g_x2f);
    cudaGetSymbolAddress((void**)&hf,   g_hf);
    cudaGetSymbolAddress((void**)&mtf,  g_mtf);
    cudaGetSymbolAddress((void**)&w1f,  g_w1f);
    cudaGetSymbolAddress((void**)&w2f,  g_w2f);
    float* mu1 = stats;
    float* rs1 = stats + B_;
    float* mu2 = stats + 2 * B_;
    float* rs2 = stats + 3 * B_;

    cudaFuncSetAttribute(gemm_f16<0>,
                         cudaFuncAttributeMaxDynamicSharedMemorySize, SMEM_F16);
    cudaFuncSetAttribute(gemm_f16<1>,
                         cudaFuncAttributeMaxDynamicSharedMemorySize, SMEM_F16);
    cudaFuncSetAttribute(gemm_f16<2>,
                         cudaFuncAttributeMaxDynamicSharedMemorySize, SMEM_F16);

    // 0) weight prep (tril-masked Mtri, d1_w, d2_w -> fp16)
    split_w<<<dim3(1024, 3), 256>>>(triM, d1w, d2w);

    // 1) stats of inputs
    stats_part<<<dim3(16, B_), 256>>>(inputs, part);
    stats_fin<<<1, B_>>>(part, mu1, rs1);

    // 2) X1T = fp16(transpose(LN1(inputs)))
    ln1t<<<dim3(T_ / 32, C_ / 32, B_), dim3(32, 8)>>>(inputs, ln1w, ln1b, mu1, rs1,
                                                       x1tf);

    // 3) Y = tril(M) @ X1 + tri_b + inputs   (fp16 MMA)
    gemm_f16<0><<<dim3(4, 4, B_), 256, SMEM_F16>>>(mtf, x1tf, trib, inputs,
                                                    Ybuf, nullptr);

    // 4) stats of Y
    stats_part<<<dim3(16, B_), 256>>>(Ybuf, part);
    stats_fin<<<1, B_>>>(part, mu2, rs2);

    // 5) X2 = LN2(Y)  (fp32 + fp16)
    ln_apply2<<<dim3(NTC / 4 / 256, B_), 256>>>(Ybuf, ln2w, ln2b, mu2, rs2,
                                                X2buf, x2f);

    // 6) H = fp16(gelu(X2 @ d1_w^T + d1_b))
    gemm_f16<1><<<dim3(4, 256), 256, SMEM_F16>>>(x2f, w1f, d1b, nullptr,
                                                 nullptr, hf);

    // 7) out = X2 + H @ d2_w^T + d2_b
    gemm_f16<2><<<dim3(4, 256), 256, SMEM_F16>>>(hf, w2f, d2b, X2buf,
                                                 out, nullptr);
}

// round 16
// speedup vs baseline: 3.9710x; 1.2272x over previous
#include <cuda_runtime.h>
#include <cuda_fp16.h>
#include <math.h>
#include <stdint.h>

#define B_  64
#define T_  512
#define C_  512
#define NTC (T_ * C_)
#define TOT (B_ * T_ * C_)

// ---------------- scratch (__device__ globals; no allocation allowed) -------
__device__ float g_part[B_ * 16 * 2];
__device__ float g_stats[4 * B_];
__device__ __align__(16) __half g_yf[TOT];        // tri-mix output fp16
__device__ __align__(16) __half g_x1tf[TOT];      // LN1^T fp16
__device__ __align__(16) __half g_x2f[TOT];       // LN2 out fp16 (GEMM1 A + GEMM2 residual)
__device__ __align__(16) __half g_hf[TOT];        // gelu out fp16
__device__ __align__(16) __half g_mtf[T_ * T_];   // tril-masked Mtri fp16
__device__ __align__(16) __half g_w1f[C_ * C_], g_w2f[C_ * C_];

// ---------------- PTX helpers (sm_80-class: valid on compute_103) ----------
__device__ __forceinline__ uint32_t smem_u32(const void* p) {
    uint32_t a;
    asm("{ .reg .u64 t; cvta.to.shared.u64 t, %1; cvt.u32.u64 %0, t; }"
        : "=r"(a) : "l"(p));
    return a;
}
__device__ __forceinline__ void ldmx4(uint32_t* r, uint32_t a) {
    asm volatile("ldmatrix.sync.aligned.m8n8.x4.shared.b16 {%0,%1,%2,%3}, [%4];"
                 : "=r"(r[0]), "=r"(r[1]), "=r"(r[2]), "=r"(r[3]) : "r"(a));
}
__device__ __forceinline__ void mma_f16(float* c, const uint32_t* a, const uint32_t* b) {
    asm volatile(
        "mma.sync.aligned.m16n8k16.row.col.f32.f16.f16.f32 "
        "{%0,%1,%2,%3}, {%4,%5,%6,%7}, {%8,%9}, {%0,%1,%2,%3};"
        : "+f"(c[0]), "+f"(c[1]), "+f"(c[2]), "+f"(c[3])
        : "r"(a[0]), "r"(a[1]), "r"(a[2]), "r"(a[3]), "r"(b[0]), "r"(b[1]));
}
__device__ __forceinline__ void cp16(uint32_t sdst, const void* gsrc) {
    asm volatile("cp.async.cg.shared.global [%0], [%1], 16;"
                 :: "r"(sdst), "l"(gsrc));
}
#define CP_COMMIT() asm volatile("cp.async.commit_group;" ::: "memory")
#define CP_WAIT(n)  asm volatile("cp.async.wait_group %0;" :: "n"(n) : "memory")

// smem tile: 128 rows x 32 fp16 (64B), padded to 80B/row (conflict-free ldmatrix)
#define STRIDE   80
#define TILE_B   (128 * STRIDE)          // 10240
#define F1_STAGE (2 * TILE_B)            // 20480 (A tile + B tile)
#define SMEM_F16 (2 * F1_STAGE)          // 40960 (double buffered)

// common fragment-load + MMA inner step
#define GEMM_CORE(aB, bB)                                                     \
    _Pragma("unroll")                                                         \
    for (int ks = 0; ks < 2; ++ks) {                                          \
        int kso = ks * 32;                                                    \
        uint32_t ah[4][4], bh[4][2];                                          \
        _Pragma("unroll")                                                     \
        for (int mi = 0; mi < 4; ++mi)                                        \
            ldmx4(ah[mi], (aB) + mi * (16 * STRIDE) + kso);                   \
        _Pragma("unroll")                                                     \
        for (int jj = 0; jj < 2; ++jj) {                                      \
            uint32_t t4[4];                                                   \
            ldmx4(t4, (bB) + jj * (16 * STRIDE) + kso);                       \
            bh[2 * jj][0] = t4[0]; bh[2 * jj][1] = t4[1];                     \
            bh[2 * jj + 1][0] = t4[2]; bh[2 * jj + 1][1] = t4[3];             \
        }                                                                     \
        _Pragma("unroll")                                                     \
        for (int mi = 0; mi < 4; ++mi)                                        \
            _Pragma("unroll")                                                 \
            for (int ni = 0; ni < 4; ++ni)                                    \
                mma_f16(acc[mi][ni], ah[mi], bh[ni]);                         \
    }

// ---------------------------------------------------------------------------
// Tri GEMM: Yh[b,m,n] = fp16( sum_{k<=diag} Mtri[m,k]*X1T[b,n,k] + trib[m]
//                             + inputs[b,m,n] )
// Also emits per-CTA partial (sum, sumsq) of its fp32 tile -> part[bz*16+tile].
// ---------------------------------------------------------------------------
__global__ __launch_bounds__(256, 2)
void gemm_tri(const __half* __restrict__ AG, const __half* __restrict__ BGall,
              const float* __restrict__ bias, const float* __restrict__ ResAll,
              __half* __restrict__ OutYall, float* __restrict__ part) {
    extern __shared__ char smem[];
    const int Kd = 512;
    int tid = threadIdx.x, wid = tid >> 5, lane = tid & 31;
    int n0 = blockIdx.x * 128, m0 = blockIdx.y * 128;
    size_t bz = blockIdx.z;
    const __half* BG = BGall + bz * NTC;
    const float* Res = ResAll + bz * NTC;
    __half* OutY = OutYall + bz * NTC;

    uint32_t sb = smem_u32(smem);
    float acc[4][4][4];
#pragma unroll
    for (int i = 0; i < 4; i++)
#pragma unroll
        for (int j = 0; j < 4; j++)
#pragma unroll
            for (int e = 0; e < 4; e++) acc[i][j][e] = 0.f;

    int nch = (m0 + 128) / 32;          // K truncated at diagonal tile

    auto load_tile = [&](const __half* G, int row0, uint32_t dst, int k0) {
#pragma unroll
        for (int it = 0; it < 2; ++it) {
            int seg = tid + it * 256;
            int r = seg >> 2, c8 = (seg & 3) * 8;
            size_t go = (size_t)(row0 + r) * Kd + k0 + c8;
            cp16(dst + (uint32_t)(r * STRIDE + c8 * 2), G + go);
        }
    };
    auto load_chunk = [&](int c, int s) {
        uint32_t base = sb + s * F1_STAGE;
        int k0 = c * 32;
        load_tile(AG, m0, base, k0);
        load_tile(BG, n0, base + TILE_B, k0);
    };

    int aRow = (wid & 1) * 64 + ((lane >> 3) & 1) * 8 + (lane & 7);
    int aCol = (lane >> 4) * 16;
    int bRow = (wid >> 1) * 32 + (lane >> 4) * 8 + (lane & 7);
    int bCol = ((lane >> 3) & 1) * 16;

    load_chunk(0, 0);
    CP_COMMIT();

    for (int c = 0; c < nch; ++c) {
        int s = c & 1;
        if (c + 1 < nch) { load_chunk(c + 1, s ^ 1); CP_COMMIT(); CP_WAIT(1); }
        else             { CP_WAIT(0); }
        __syncthreads();
        uint32_t aB = sb + s * F1_STAGE + aRow * STRIDE + aCol;
        uint32_t bB = sb + s * F1_STAGE + TILE_B + bRow * STRIDE + bCol;
        GEMM_CORE(aB, bB)
        __syncthreads();
    }

    // epilogue: bias + residual, write fp16 Y, accumulate tile stats
    int mwb = m0 + (wid & 1) * 64;
    int nwb = n0 + (wid >> 1) * 32;
    int mr = lane >> 2, nc = (lane & 3) * 2;
    float s = 0.f, s2 = 0.f;
#pragma unroll
    for (int mi = 0; mi < 4; ++mi)
#pragma unroll
        for (int ni = 0; ni < 4; ++ni) {
            int n = nwb + ni * 8 + nc;
#pragma unroll
            for (int half = 0; half < 2; ++half) {
                int m = mwb + mi * 16 + mr + half * 8;
                float tb = bias[m];
                float2 rv = *(const float2*)(Res + (size_t)m * 512 + n);
                float v0 = acc[mi][ni][half * 2 + 0] + tb + rv.x;
                float v1 = acc[mi][ni][half * 2 + 1] + tb + rv.y;
                s  += v0 + v1;
                s2 += v0 * v0 + v1 * v1;
                *(__half2*)(OutY + (size_t)m * 512 + n) = __floats2half2_rn(v0, v1);
            }
        }
    // deterministic block reduction into unique slot
    __syncthreads();
    float* sh  = (float*)smem;
    float* sh2 = sh + 256;
    sh[tid] = s; sh2[tid] = s2;
    __syncthreads();
    for (int o = 128; o > 0; o >>= 1) {
        if (tid < o) { sh[tid] += sh[tid + o]; sh2[tid] += sh2[tid + o]; }
        __syncthreads();
    }
    if (tid == 0) {
        int slot = (int)bz * 16 + blockIdx.y * 4 + blockIdx.x;
        part[slot * 2 + 0] = sh[0];
        part[slot * 2 + 1] = sh2[0];
    }
}

// ---------------------------------------------------------------------------
// Dense MLP GEMM. MODE 1: OutH = fp16(gelu(acc + bias[n]))
//                 MODE 2: OutF = acc + bias[n] + fp32(ResH[m,n])
// ---------------------------------------------------------------------------
template <int MODE>
__global__ __launch_bounds__(256, 2)
void gemm_f16(const __half* __restrict__ AG, const __half* __restrict__ BG,
              const float* __restrict__ bias, const __half* __restrict__ ResH,
              float* __restrict__ OutF, __half* __restrict__ OutH) {
    extern __shared__ char smem[];
    const int Kd = 512;
    int tid = threadIdx.x, wid = tid >> 5, lane = tid & 31;
    int n0 = blockIdx.x * 128, m0 = blockIdx.y * 128;

    uint32_t sb = smem_u32(smem);
    float acc[4][4][4];
#pragma unroll
    for (int i = 0; i < 4; i++)
#pragma unroll
        for (int j = 0; j < 4; j++)
#pragma unroll
            for (int e = 0; e < 4; e++) acc[i][j][e] = 0.f;

    auto load_tile = [&](const __half* G, int row0, uint32_t dst, int k0) {
#pragma unroll
        for (int it = 0; it < 2; ++it) {
            int seg = tid + it * 256;
            int r = seg >> 2, c8 = (seg & 3) * 8;
            size_t go = (size_t)(row0 + r) * Kd + k0 + c8;
            cp16(dst + (uint32_t)(r * STRIDE + c8 * 2), G + go);
        }
    };
    auto load_chunk = [&](int c, int s) {
        uint32_t base = sb + s * F1_STAGE;
        int k0 = c * 32;
        load_tile(AG, m0, base, k0);
        load_tile(BG, n0, base + TILE_B, k0);
    };

    int aRow = (wid & 1) * 64 + ((lane >> 3) & 1) * 8 + (lane & 7);
    int aCol = (lane >> 4) * 16;
    int bRow = (wid >> 1) * 32 + (lane >> 4) * 8 + (lane & 7);
    int bCol = ((lane >> 3) & 1) * 16;

    load_chunk(0, 0);
    CP_COMMIT();

    for (int c = 0; c < 16; ++c) {
        int s = c & 1;
        if (c + 1 < 16) { load_chunk(c + 1, s ^ 1); CP_COMMIT(); CP_WAIT(1); }
        else            { CP_WAIT(0); }
        __syncthreads();
        uint32_t aB = sb + s * F1_STAGE + aRow * STRIDE + aCol;
        uint32_t bB = sb + s * F1_STAGE + TILE_B + bRow * STRIDE + bCol;
        GEMM_CORE(aB, bB)
        __syncthreads();
    }

    int mwb = m0 + (wid & 1) * 64;
    int nwb = n0 + (wid >> 1) * 32;
    int mr = lane >> 2, nc = (lane & 3) * 2;
#pragma unroll
    for (int mi = 0; mi < 4; ++mi)
#pragma unroll
        for (int ni = 0; ni < 4; ++ni) {
            int n = nwb + ni * 8 + nc;
#pragma unroll
            for (int half = 0; half < 2; ++half) {
                int m = mwb + mi * 16 + mr + half * 8;
                float v0 = acc[mi][ni][half * 2 + 0];
                float v1 = acc[mi][ni][half * 2 + 1];
                float2 bb = *(const float2*)(bias + n);
                if (MODE == 1) {
                    float t0 = v0 + bb.x, t1 = v1 + bb.y;
                    float h0 = 0.5f * t0 * (1.0f + erff(t0 * 0.70710678118654752f));
                    float h1 = 0.5f * t1 * (1.0f + erff(t1 * 0.70710678118654752f));
                    *(__half2*)(OutH + (size_t)m * 512 + n) = __floats2half2_rn(h0, h1);
                } else {
                    __half2 rv = *(const __half2*)(ResH + (size_t)m * 512 + n);
                    v0 += bb.x + __low2float(rv);
                    v1 += bb.y + __high2float(rv);
                    *(float2*)(OutF + (size_t)m * 512 + n) = make_float2(v0, v1);
                }
            }
        }
}

// ---------------------------------------------------------------------------
// Weight prep: z=0 Mtri -> tril-masked fp16; z=1 w1 -> fp16; z=2 w2 -> fp16
// ---------------------------------------------------------------------------
__global__ void split_w(const float* __restrict__ Mt, const float* __restrict__ w1,
                        const float* __restrict__ w2) {
    int idx = blockIdx.x * 256 + threadIdx.x;
    int z = blockIdx.y;
    if (z == 0) {
        int i = idx >> 9, j = idx & 511;
        float v = (j <= i) ? Mt[idx] : 0.f;
        g_mtf[idx] = __float2half(v);
    } else if (z == 1) {
        g_w1f[idx] = __float2half(w1[idx]);
    } else {
        g_w2f[idx] = __float2half(w2[idx]);
    }
}

// ---------------------------------------------------------------------------
// Per-batch stats of fp32 input, split 16 ways (deterministic two-pass).
// ---------------------------------------------------------------------------
__global__ void stats_part(const float* __restrict__ x, float* __restrict__ part) {
    int b = blockIdx.y, slice = blockIdx.x;
    const float4* p = (const float4*)(x + (size_t)b * NTC) + (size_t)slice * 4096;
    float s = 0.f, s2 = 0.f;
    for (int i = threadIdx.x; i < 4096; i += 256) {
        float4 v = p[i];
        s  += v.x + v.y + v.z + v.w;
        s2 += v.x * v.x + v.y * v.y + v.z * v.z + v.w * v.w;
    }
    __shared__ float sh[256], sh2[256];
    sh[threadIdx.x] = s; sh2[threadIdx.x] = s2;
    __syncthreads();
    for (int o = 128; o > 0; o >>= 1) {
        if (threadIdx.x < o) {
            sh[threadIdx.x] += sh[threadIdx.x + o];
            sh2[threadIdx.x] += sh2[threadIdx.x + o];
        }
        __syncthreads();
    }
    if (threadIdx.x == 0) {
        part[(b * 16 + slice) * 2 + 0] = sh[0];
        part[(b * 16 + slice) * 2 + 1] = sh2[0];
    }
}
__global__ void stats_fin(const float* __restrict__ part, float* __restrict__ mu,
                          float* __restrict__ rs) {
    int b = threadIdx.x;
    float s = 0.f, s2 = 0.f;
    for (int i = 0; i < 16; ++i) {
        s  += part[(b * 16 + i) * 2 + 0];
        s2 += part[(b * 16 + i) * 2 + 1];
    }
    float m = s / (float)NTC;
    float var = s2 / (float)NTC - m * m;
    mu[b] = m;
    rs[b] = rsqrtf(var + 1e-5f);
}

// ---------------------------------------------------------------------------
// LN1 + transpose -> fp16: x1tf[b][c][t]
// ---------------------------------------------------------------------------
__global__ void ln1t(const float* __restrict__ x, const float* __restrict__ w,
                     const float* __restrict__ bias, const float* __restrict__ mu,
                     const float* __restrict__ rs, __half* __restrict__ xtf) {
    __shared__ float tile[32][33];
    int b = blockIdx.z;
    int t0 = blockIdx.x * 32, c0 = blockIdx.y * 32;
    float m = mu[b], r = rs[b];
    int tx = threadIdx.x, ty = threadIdx.y;
#pragma unroll
    for (int k = 0; k < 4; ++k) {
        int t = t0 + ty + k * 8, c = c0 + tx;
        size_t idx = (size_t)t * C_ + c;
        tile[ty + k * 8][tx] = (x[(size_t)b * NTC + idx] - m) * r * w[idx] + bias[idx];
    }
    __syncthreads();
#pragma unroll
    for (int k = 0; k < 4; ++k) {
        int c = c0 + ty + k * 8, t = t0 + tx;
        xtf[(size_t)b * NTC + (size_t)c * T_ + t] = __float2half(tile[tx][ty + k * 8]);
    }
}

// ---------------------------------------------------------------------------
// LN2 apply on fp16 Y -> fp16 X2 (4 elems/thread).
// ---------------------------------------------------------------------------
__global__ void ln_apply2(const __half* __restrict__ y, const float* __restrict__ w,
                          const float* __restrict__ bias, const float* __restrict__ mu,
                          const float* __restrict__ rs, __half* __restrict__ outh) {
    int b = blockIdx.y;
    int idx = blockIdx.x * blockDim.x + threadIdx.x;   // uint2 index (4 halves)
    float m = mu[b], r = rs[b];
    uint2 yv = ((const uint2*)(y + (size_t)b * NTC))[idx];
    __half2 y01 = *(__half2*)&yv.x;
    __half2 y23 = *(__half2*)&yv.y;
    float4 wv = ((const float4*)w)[idx];
    float4 bv = ((const float4*)bias)[idx];
    float o0 = (__low2float(y01)  - m) * r * wv.x + bv.x;
    float o1 = (__high2float(y01) - m) * r * wv.y + bv.y;
    float o2 = (__low2float(y23)  - m) * r * wv.z + bv.z;
    float o3 = (__high2float(y23) - m) * r * wv.w + bv.w;
    __half2 h01 = __floats2half2_rn(o0, o1);
    __half2 h23 = __floats2half2_rn(o2, o3);
    uint32_t u01, u23;
    memcpy(&u01, &h01, 4);
    memcpy(&u23, &h23, 4);
    ((uint2*)(outh + (size_t)b * NTC))[idx] = make_uint2(u01, u23);
}

// ---------------------------------------------------------------------------
extern "C" void kernel_launch(void* const* d_in, const int* in_sizes, int n_in,
                              void* d_out, int out_size) {
    const float* inputs = (const float*)d_in[0];
    const float* ln1w   = (const float*)d_in[1];
    const float* ln1b   = (const float*)d_in[2];
    const float* ln2w   = (const float*)d_in[3];
    const float* ln2b   = (const float*)d_in[4];
    const float* triM   = (const float*)d_in[5];
    const float* trib   = (const float*)d_in[6];
    const float* d1w    = (const float*)d_in[7];
    const float* d1b    = (const float*)d_in[8];
    const float* d2w    = (const float*)d_in[9];
    const float* d2b    = (const float*)d_in[10];
    float* out = (float*)d_out;

    float *part, *stats;
    __half *yf, *x1tf, *x2f, *hf, *mtf, *w1f, *w2f;
    cudaGetSymbolAddress((void**)&part,  g_part);
    cudaGetSymbolAddress((void**)&stats, g_stats);
    cudaGetSymbolAddress((void**)&yf,   g_yf);
    cudaGetSymbolAddress((void**)&x1tf, g_x1tf);
    cudaGetSymbolAddress((void**)&x2f,  g_x2f);
    cudaGetSymbolAddress((void**)&hf,   g_hf);
    cudaGetSymbolAddress((void**)&mtf,  g_mtf);
    cudaGetSymbolAddress((void**)&w1f,  g_w1f);
    cudaGetSymbolAddress((void**)&w2f,  g_w2f);
    float* mu1 = stats;
    float* rs1 = stats + B_;
    float* mu2 = stats + 2 * B_;
    float* rs2 = stats + 3 * B_;

    cudaFuncSetAttribute(gemm_tri,
                         cudaFuncAttributeMaxDynamicSharedMemorySize, SMEM_F16);
    cudaFuncSetAttribute(gemm_f16<1>,
                         cudaFuncAttributeMaxDynamicSharedMemorySize, SMEM_F16);
    cudaFuncSetAttribute(gemm_f16<2>,
                         cudaFuncAttributeMaxDynamicSharedMemorySize, SMEM_F16);

    // 0) weight prep (tril-masked Mtri, d1_w, d2_w -> fp16)
    split_w<<<dim3(1024, 3), 256>>>(triM, d1w, d2w);

    // 1) stats of inputs
    stats_part<<<dim3(16, B_), 256>>>(inputs, part);
    stats_fin<<<1, B_>>>(part, mu1, rs1);

    // 2) X1T = fp16(transpose(LN1(inputs)))
    ln1t<<<dim3(T_ / 32, C_ / 32, B_), dim3(32, 8)>>>(inputs, ln1w, ln1b, mu1, rs1,
                                                       x1tf);

    // 3) Yh = fp16(tril(M) @ X1 + tri_b + inputs), fused per-tile stats
    gemm_tri<<<dim3(4, 4, B_), 256, SMEM_F16>>>(mtf, x1tf, trib, inputs, yf, part);

    // 4) finalize Y stats from trigemm partials
    stats_fin<<<1, B_>>>(part, mu2, rs2);

    // 5) X2 = fp16(LN2(Y))
    ln_apply2<<<dim3(NTC / 4 / 256, B_), 256>>>(yf, ln2w, ln2b, mu2, rs2, x2f);

    // 6) H = fp16(gelu(X2 @ d1_w^T + d1_b))
    gemm_f16<1><<<dim3(4, 256), 256, SMEM_F16>>>(x2f, w1f, d1b, nullptr,
                                                 nullptr, hf);

    // 7) out = X2 + H @ d2_w^T + d2_b
    gemm_f16<2><<<dim3(4, 256), 256, SMEM_F16>>>(hf, w2f, d2b, x2f,
                                                 out, nullptr);
}